// round 2
// baseline (speedup 1.0000x reference)
#include <cuda_runtime.h>
#include <math.h>
#include <float.h>

#define BB   8
#define NPTS 2048
#define KNB  32
#define MSEL 1024
#define SCL  0.08838834764831845f

// ---------------- scratch pool (static device memory, no allocs) ----------
static constexpr long NT    = (long)BB*128*NPTS;              // 2,097,152
static constexpr long O_S   = 0;                               // 8*2048*2048
static constexpr long O_B1  = O_S  + (long)BB*NPTS*NPTS;
static constexpr long O_B2  = O_B1 + (long)BB*1024*NPTS;
static constexpr long O_F   = O_B2 + (long)BB*1024*NPTS;       // 512ch
static constexpr long O_E0  = O_F  + (long)BB*512*NPTS;
static constexpr long O_E1  = O_E0 + NT;
static constexpr long O_H   = O_E1 + NT;                       // 256ch
static constexpr long O_HF  = O_H  + 2*NT;
static constexpr long O_HU  = O_HF + NT;
static constexpr long O_T1  = O_HU + NT;
static constexpr long O_T2  = O_T1 + NT;
static constexpr long O_T3  = O_T2 + NT;
static constexpr long O_T4  = O_T3 + NT;
static constexpr long O_T5  = O_T4 + NT;
static constexpr long O_T6  = O_T5 + NT;
static constexpr long O_Y   = O_T6 + NT;
static constexpr long O_XT  = O_Y  + NT;
static constexpr long O_HD  = O_XT + NT;                       // 8*128*1024
static constexpr long O_HD2 = O_HD + (long)BB*128*MSEL;
static constexpr long O_SQ  = O_HD2+ (long)BB*128*MSEL;
static constexpr long O_RM  = O_SQ + BB*NPTS;
static constexpr long O_RI  = O_RM + BB*NPTS;
static constexpr long O_SC  = O_RI + BB*NPTS;
static constexpr long O_GV  = O_SC + BB*NPTS;                  // 8*2112
static constexpr long O_CV  = O_GV + BB*2112;                  // 8*1024
static constexpr long O_MU  = O_CV + BB*1024;
static constexpr long O_IS  = O_MU + 1024;
static constexpr long O_WD  = O_IS + 1024;                     // 128*128
static constexpr long POOLSZ= O_WD + 128*128;

__device__ __align__(128) float g_pool[POOLSZ];
__device__ int g_ipool[(long)BB*NPTS*KNB + BB*MSEL];
static constexpr long SELOFF = (long)BB*NPTS*KNB;

// ---------------- generic strided-batch TN SGEMM --------------------------
// C[b,i,j] = sum_k A[b*abs + k*ask + i*asi] * B[b*bbs + k*bsk + j*bsj]
__global__ void gemm_tn(const float* __restrict__ A, const float* __restrict__ B,
                        float* __restrict__ C, int Kd, int I, int J,
                        long abs_, long ask, long asi,
                        long bbs, long bsk, long bsj, long cbs)
{
    __shared__ float As[16][68];
    __shared__ float Bs[16][68];
    const int tid = threadIdx.x, tx = tid & 15, ty = tid >> 4;
    A += (long)blockIdx.z * abs_; B += (long)blockIdx.z * bbs;
    C += (long)blockIdx.z * cbs;
    const int i0 = blockIdx.y * 64, j0 = blockIdx.x * 64;
    float acc[4][4] = {};
    for (int k0 = 0; k0 < Kd; k0 += 16) {
#pragma unroll
        for (int it = 0; it < 4; it++) {
            int l = tid + it * 256, ii = l & 63, kk = l >> 6;
            int i = i0 + ii, k = k0 + kk;
            As[kk][ii] = (i < I && k < Kd) ? A[k*ask + i*asi] : 0.f;
        }
#pragma unroll
        for (int it = 0; it < 4; it++) {
            int l = tid + it * 256, jj = l & 63, kk = l >> 6;
            int j = j0 + jj, k = k0 + kk;
            Bs[kk][jj] = (j < J && k < Kd) ? B[k*bsk + j*bsj] : 0.f;
        }
        __syncthreads();
#pragma unroll
        for (int kk = 0; kk < 16; kk++) {
            float ar[4], br[4];
#pragma unroll
            for (int u = 0; u < 4; u++) ar[u] = As[kk][ty*4+u];
#pragma unroll
            for (int u = 0; u < 4; u++) br[u] = Bs[kk][tx*4+u];
#pragma unroll
            for (int a = 0; a < 4; a++)
#pragma unroll
                for (int b2 = 0; b2 < 4; b2++) acc[a][b2] += ar[a]*br[b2];
        }
        __syncthreads();
    }
#pragma unroll
    for (int a = 0; a < 4; a++) {
        int i = i0 + ty*4 + a; if (i >= I) continue;
#pragma unroll
        for (int b2 = 0; b2 < 4; b2++) {
            int j = j0 + tx*4 + b2;
            if (j < J) C[(long)i*J + j] = acc[a][b2];
        }
    }
}

// sq[b,n] = sum_c X[b,c,n]^2   (X layout (b,c,n))
__global__ void colnorm_k(const float* __restrict__ X, float* __restrict__ sq,
                          int C, int Np)
{
    int i = blockIdx.x*blockDim.x + threadIdx.x;
    if (i >= BB*Np) return;
    int b = i/Np, n = i%Np;
    const float* p = X + (long)b*C*Np + n;
    float s = 0.f;
    for (int c = 0; c < C; c++) { float v = p[(long)c*Np]; s += v*v; }
    sq[i] = s;
}

// per-row top-32 smallest distances, tie-break lower index (matches jax)
__global__ void knn_topk(const float* __restrict__ S, const float* __restrict__ sq,
                         int* __restrict__ idx, int Np)
{
    extern __shared__ float sd[];
    __shared__ float wv[8]; __shared__ int wi[8];
    int bn = blockIdx.x, b = bn/Np, n = bn%Np, tid = threadIdx.x;
    const float* Srow = S + ((long)b*Np + n)*Np;
    float sn = sq[(long)b*Np + n];
    for (int m = tid; m < Np; m += 256)
        sd[m] = sn - 2.f*Srow[m] + sq[(long)b*Np + m];
    __syncthreads();
    int lane = tid & 31, w = tid >> 5;
    for (int k = 0; k < KNB; k++) {
        float bv = FLT_MAX; int bi = 0x7fffffff;
        for (int m = tid; m < Np; m += 256) {
            float v = sd[m];
            if (v < bv) { bv = v; bi = m; }
        }
#pragma unroll
        for (int o = 16; o > 0; o >>= 1) {
            float ov = __shfl_down_sync(0xffffffffu, bv, o);
            int   oi = __shfl_down_sync(0xffffffffu, bi, o);
            if (ov < bv || (ov == bv && oi < bi)) { bv = ov; bi = oi; }
        }
        if (lane == 0) { wv[w] = bv; wi[w] = bi; }
        __syncthreads();
        if (tid == 0) {
            float rv = wv[0]; int ri = wi[0];
            for (int j = 1; j < 8; j++)
                if (wv[j] < rv || (wv[j] == rv && wi[j] < ri)) { rv = wv[j]; ri = wi[j]; }
            idx[((long)b*Np + n)*KNB + k] = ri;
            sd[ri] = FLT_MAX;
        }
        __syncthreads();
    }
}

// Wd[o,c] = W[o,c] - W[o,Cin+c],  W is (O, 2*Cin)
__global__ void wdiff_k(const float* __restrict__ W, float* __restrict__ Wd,
                        int O, int Cin)
{
    int i = blockIdx.x*blockDim.x + threadIdx.x;
    if (i < O*Cin) {
        int o = i/Cin, c = i%Cin;
        Wd[i] = W[o*2*Cin + c] - W[o*2*Cin + Cin + c];
    }
}

// Ut,Vt in (b,n,o); outputs max/sum/sumsq over k in (b,o,n)
__global__ void edge_assemble(const float* __restrict__ Ut, const float* __restrict__ Vt,
                              const int* __restrict__ idx,
                              float* __restrict__ Ym, float* __restrict__ Ys,
                              float* __restrict__ Yq, int Np)
{
    int bn = blockIdx.x, b = bn/Np, n = bn%Np, o = threadIdx.x;
    float u = Ut[(long)bn*128 + o];
    const int* ip = idx + (long)bn*KNB;
    const float* vb = Vt + (long)b*Np*128;
    float mx = -FLT_MAX, s = 0.f, q = 0.f;
#pragma unroll 4
    for (int k = 0; k < KNB; k++) {
        int m = ip[k];
        float v = u + vb[(long)m*128 + o];
        mx = fmaxf(mx, v); s += v; q += v*v;
    }
    long off = ((long)b*128 + o)*Np + n;
    Ym[off] = mx; Ys[off] = s; Yq[off] = q;
}

__global__ void stats_sums(const float* __restrict__ S1, const float* __restrict__ S2,
                           float* __restrict__ mu, float* __restrict__ is,
                           int O, int Np, long cnt)
{
    int o = blockIdx.x, tid = threadIdx.x;
    double s = 0, q = 0;
    for (int b = 0; b < BB; b++) {
        const float* p1 = S1 + ((long)b*O + o)*Np;
        const float* p2 = S2 + ((long)b*O + o)*Np;
        for (int n = tid; n < Np; n += 256) { s += p1[n]; q += p2[n]; }
    }
    __shared__ double ss[256], qq[256];
    ss[tid] = s; qq[tid] = q; __syncthreads();
    for (int st = 128; st > 0; st >>= 1) {
        if (tid < st) { ss[tid] += ss[tid+st]; qq[tid] += qq[tid+st]; }
        __syncthreads();
    }
    if (tid == 0) {
        double m = ss[0]/(double)cnt, v = qq[0]/(double)cnt - m*m;
        mu[o] = (float)m; is[o] = (float)(1.0/sqrt(v + 1e-5));
    }
}

__global__ void stats_tensor(const float* __restrict__ X, float* __restrict__ mu,
                             float* __restrict__ is, int O, int Np, long cnt)
{
    int o = blockIdx.x, tid = threadIdx.x;
    double s = 0, q = 0;
    for (int b = 0; b < BB; b++) {
        const float* p = X + ((long)b*O + o)*Np;
        for (int n = tid; n < Np; n += 256) { double v = p[n]; s += v; q += v*v; }
    }
    __shared__ double ss[256], qq[256];
    ss[tid] = s; qq[tid] = q; __syncthreads();
    for (int st = 128; st > 0; st >>= 1) {
        if (tid < st) { ss[tid] += ss[tid+st]; qq[tid] += qq[tid+st]; }
        __syncthreads();
    }
    if (tid == 0) {
        double m = ss[0]/(double)cnt, v = qq[0]/(double)cnt - m*m;
        mu[o] = (float)m; is[o] = (float)(1.0/sqrt(v + 1e-5));
    }
}

// Y = [res +] leaky((X - mu[o]) * is[o]),  X layout (b,O,Np)
__global__ void bn_leaky(const float* __restrict__ X, const float* __restrict__ res,
                         float* __restrict__ Y, const float* __restrict__ mu,
                         const float* __restrict__ is, int O, int Np, long total)
{
    long i = (long)blockIdx.x*blockDim.x + threadIdx.x;
    if (i >= total) return;
    int o = (int)((i / Np) % O);
    float v = (X[i] - mu[o]) * is[o];
    v = v > 0.f ? v : 0.2f*v;
    Y[i] = res ? res[i] + v : v;
}

__global__ void concat2_k(const float* __restrict__ A, const float* __restrict__ B,
                          float* __restrict__ H, int C, int Np, long total)
{
    long i = (long)blockIdx.x*blockDim.x + threadIdx.x;
    if (i >= total) return;
    long per = (long)2*C*Np;
    int b = (int)(i/per); long r = i % per;
    int c = (int)(r/Np), n = (int)(r%Np);
    H[i] = (c < C) ? A[((long)b*C + c)*Np + n] : B[((long)b*C + c - C)*Np + n];
}

// warp-per-query local attention; qt/kt/vt/out in (b,n,c), c=128, K=32
__global__ void n2p_core(const float* __restrict__ qt, const float* __restrict__ kt,
                         const float* __restrict__ vt, const int* __restrict__ idx,
                         float* __restrict__ outt, int Np, float scale)
{
    __shared__ float qsh[4][128];
    int warp = threadIdx.x >> 5, lane = threadIdx.x & 31;
    long bn = (long)blockIdx.x*4 + warp;
    int b = (int)(bn/Np), n = (int)(bn%Np);
    const float* qp = qt + ((long)b*Np + n)*128;
    for (int c = lane; c < 128; c += 32) qsh[warp][c] = qp[c];
    __syncwarp();
    int m = idx[((long)b*Np + n)*KNB + lane];
    const float4* krow = (const float4*)(kt + ((long)b*Np + m)*128);
    float dot = 0.f;
#pragma unroll
    for (int c4 = 0; c4 < 32; c4++) {
        float4 kv = krow[c4];
        dot += qsh[warp][c4*4+0]*kv.x + qsh[warp][c4*4+1]*kv.y +
               qsh[warp][c4*4+2]*kv.z + qsh[warp][c4*4+3]*kv.w;
    }
    float logit = dot * scale, mx = logit;
#pragma unroll
    for (int o = 16; o > 0; o >>= 1) mx = fmaxf(mx, __shfl_xor_sync(0xffffffffu, mx, o));
    float e = __expf(logit - mx), sum = e;
#pragma unroll
    for (int o = 16; o > 0; o >>= 1) sum += __shfl_xor_sync(0xffffffffu, sum, o);
    float a = e / sum;
    const float* vbase = vt + (long)b*Np*128;
    float acc[4] = {0.f, 0.f, 0.f, 0.f};
#pragma unroll
    for (int k = 0; k < KNB; k++) {
        float ak = __shfl_sync(0xffffffffu, a, k);
        int  mk = __shfl_sync(0xffffffffu, m, k);
        const float* vr = vbase + (long)mk*128;
#pragma unroll
        for (int cb = 0; cb < 4; cb++) acc[cb] += ak * vr[cb*32 + lane];
    }
    float* op = outt + ((long)b*Np + n)*128;
#pragma unroll
    for (int cb = 0; cb < 4; cb++) op[cb*32 + lane] = acc[cb];
}

__global__ void row_stats(const float* __restrict__ S, float* __restrict__ rmax,
                          float* __restrict__ rinv, int Np, float scale)
{
    __shared__ float red[256];
    int bn = blockIdx.x, tid = threadIdx.x;
    const float* row = S + (long)bn*Np;
    float mx = -FLT_MAX;
    for (int m = tid; m < Np; m += 256) mx = fmaxf(mx, row[m]*scale);
    red[tid] = mx; __syncthreads();
    for (int s = 128; s > 0; s >>= 1) {
        if (tid < s) red[tid] = fmaxf(red[tid], red[tid+s]);
        __syncthreads();
    }
    float M = red[0]; __syncthreads();
    float sum = 0.f;
    for (int m = tid; m < Np; m += 256) sum += __expf(row[m]*scale - M);
    red[tid] = sum; __syncthreads();
    for (int s = 128; s > 0; s >>= 1) {
        if (tid < s) red[tid] += red[tid+s];
        __syncthreads();
    }
    if (tid == 0) { rmax[bn] = M; rinv[bn] = 1.f/red[0]; }
}

__global__ void col_score(const float* __restrict__ S, const float* __restrict__ rmax,
                          const float* __restrict__ rinv, float* __restrict__ score,
                          int Np, float scale)
{
    int b = blockIdx.y;
    int m = blockIdx.x*256 + threadIdx.x;
    if (m >= Np) return;
    const float* Sb = S + (long)b*Np*Np;
    const float* rm = rmax + (long)b*Np;
    const float* rs = rinv + (long)b*Np;
    float acc = 0.f;
#pragma unroll 4
    for (int n = 0; n < Np; n++)
        acc += __expf(Sb[(long)n*Np + m]*scale - rm[n]) * rs[n];
    score[(long)b*Np + m] = acc * (1.f/Np);
}

__global__ void topM_select(const float* __restrict__ score, int* __restrict__ sel,
                            int Np, int M)
{
    extern __shared__ float sc[];
    int b = blockIdx.x, tid = threadIdx.x;
    for (int m = tid; m < Np; m += 256) sc[m] = score[(long)b*Np + m];
    __syncthreads();
    for (int m = tid; m < Np; m += 256) {
        float v = sc[m];
        int r = 0;
        for (int j = 0; j < Np; j++) {
            float u = sc[j];
            r += (u > v) || (u == v && j < m);
        }
        if (r < M) sel[b*M + r] = m;
    }
}

__global__ void gather_cols(const float* __restrict__ X, const int* __restrict__ sel,
                            float* __restrict__ Y, int C, int Nsrc, int Mdst, long total)
{
    long i = (long)blockIdx.x*blockDim.x + threadIdx.x;
    if (i >= total) return;
    long per = (long)C*Mdst;
    int b = (int)(i/per); long r = i % per;
    int c = (int)(r/Mdst), j = (int)(r%Mdst);
    Y[i] = X[((long)b*C + c)*Nsrc + sel[b*Mdst + j]];
}

__global__ void softmax_rows(float* __restrict__ S, int cols, float scale)
{
    extern __shared__ float buf[];
    __shared__ float red[256];
    long row = blockIdx.x;
    int tid = threadIdx.x;
    float* p = S + row*cols;
    float mx = -FLT_MAX;
    for (int j = tid; j < cols; j += 256) { float v = p[j]*scale; buf[j] = v; mx = fmaxf(mx, v); }
    red[tid] = mx; __syncthreads();
    for (int s = 128; s > 0; s >>= 1) {
        if (tid < s) red[tid] = fmaxf(red[tid], red[tid+s]);
        __syncthreads();
    }
    float M = red[0]; __syncthreads();
    float sum = 0.f;
    for (int j = tid; j < cols; j += 256) { float e = __expf(buf[j]-M); buf[j] = e; sum += e; }
    red[tid] = sum; __syncthreads();
    for (int s = 128; s > 0; s >>= 1) {
        if (tid < s) red[tid] += red[tid+s];
        __syncthreads();
    }
    float inv = 1.f/red[0];
    for (int j = tid; j < cols; j += 256) p[j] = buf[j]*inv;
}

__global__ void add2_k(const float* __restrict__ A, const float* __restrict__ B,
                       float* __restrict__ Y, long total)
{
    long i = (long)blockIdx.x*blockDim.x + threadIdx.x;
    if (i < total) Y[i] = A[i] + B[i];
}

// per (b,o) max & mean over n of X (b,1024,NPTS) -> gvec[b,2112]
__global__ void chan_maxmean(const float* __restrict__ X, float* __restrict__ gvec)
{
    __shared__ float rm[256], rs[256];
    int bo = blockIdx.x, b = bo/1024, o = bo%1024, tid = threadIdx.x;
    const float* p = X + (long)bo*NPTS;
    float mx = -FLT_MAX, s = 0.f;
    for (int n = tid; n < NPTS; n += 256) { float v = p[n]; mx = fmaxf(mx, v); s += v; }
    rm[tid] = mx; rs[tid] = s; __syncthreads();
    for (int st = 128; st > 0; st >>= 1) {
        if (tid < st) { rm[tid] = fmaxf(rm[tid], rm[tid+st]); rs[tid] += rs[tid+st]; }
        __syncthreads();
    }
    if (tid == 0) {
        gvec[(long)b*2112 + o]        = rm[0];
        gvec[(long)b*2112 + 1024 + o] = rs[0]*(1.f/NPTS);
    }
}

// cid = leaky(bn(Wc1 @ category_id)) into gvec[:, 2048:2112]
__global__ void cid_k(const float* __restrict__ W, const float* __restrict__ cat,
                      float* __restrict__ gvec)
{
    int o = threadIdx.x;
    if (o >= 64) return;
    float y[8]; double s = 0, q = 0;
    for (int b = 0; b < 8; b++) {
        float a = 0.f;
        for (int c = 0; c < 16; c++) a += W[o*16+c]*cat[b*16+c];
        y[b] = a; s += a; q += (double)a*a;
    }
    double m = s/8.0, v = q/8.0 - m*m;
    float is = (float)(1.0/sqrt(v + 1e-5));
    for (int b = 0; b < 8; b++) {
        float t = (y[b] - (float)m)*is;
        gvec[(long)b*2112 + 2048 + o] = t > 0.f ? t : 0.2f*t;
    }
}

// cvec[b*1024+o] = Wc2[o, :2112] . gvec[b]
__global__ void cvec_k(const float* __restrict__ Wc2, const float* __restrict__ gvec,
                       float* __restrict__ cvec)
{
    long gid = (long)blockIdx.x*256 + threadIdx.x;
    int warp = (int)(gid >> 5), lane = (int)(gid & 31);
    if (warp >= BB*1024) return;
    int b = warp/1024, o = warp%1024;
    const float* wr = Wc2 + (long)o*2240;
    const float* gv = gvec + (long)b*2112;
    float s = 0.f;
    for (int j = lane; j < 2112; j += 32) s += wr[j]*gv[j];
#pragma unroll
    for (int t = 16; t > 0; t >>= 1) s += __shfl_down_sync(0xffffffffu, s, t);
    if (lane == 0) cvec[warp] = s;
}

__global__ void add_bias_bo(float* __restrict__ X, const float* __restrict__ cst,
                            int Np, long total)
{
    long i = (long)blockIdx.x*blockDim.x + threadIdx.x;
    if (i < total) X[i] += cst[i/Np];
}

// ---------------- host orchestration --------------------------------------
static void G(const float* A, const float* B, float* C, int Kd, int I, int J,
              long abs_, long ask, long asi, long bbs, long bsk, long bsj, long cbs)
{
    dim3 grid((J+63)/64, (I+63)/64, BB);
    gemm_tn<<<grid, 256>>>(A, B, C, Kd, I, J, abs_, ask, asi, bbs, bsk, bsj, cbs);
}

static void BN(const float* X, const float* res, float* Y, float* mu, float* is,
               int O, int Np)
{
    stats_tensor<<<O, 256>>>(X, mu, is, O, Np, (long)BB*Np);
    long tot = (long)BB*O*Np;
    bn_leaky<<<(int)((tot+255)/256), 256>>>(X, res, Y, mu, is, O, Np, tot);
}

static void KNN(const float* X, int Cin, int Np, float* P, int* idx)
{
    colnorm_k<<<(BB*Np+255)/256, 256>>>(X, P+O_SQ, Cin, Np);
    G(X, X, P+O_S, Cin, Np, Np, (long)Cin*Np, Np, 1, (long)Cin*Np, Np, 1, (long)Np*Np);
    knn_topk<<<BB*Np, 256, Np*4>>>(P+O_S, P+O_SQ, idx, Np);
}

static void N2P(const float* X, int Cin, int Np,
                const float* Wq, const float* Wk, const float* Wv, const float* Wo,
                const float* Wf1, const float* Wf2, float* outb, float* P, int* idx)
{
    KNN(X, Cin, Np, P, idx);
    long XB = (long)Cin*Np;
    G(X, Wq, P+O_T1, Cin, Np, 128, XB, Np, 1, 0, 1, Cin, (long)Np*128);
    G(X, Wk, P+O_T2, Cin, Np, 128, XB, Np, 1, 0, 1, Cin, (long)Np*128);
    G(X, Wv, P+O_T3, Cin, Np, 128, XB, Np, 1, 0, 1, Cin, (long)Np*128);
    n2p_core<<<BB*Np/4, 128>>>(P+O_T1, P+O_T2, P+O_T3, idx, P+O_T4, Np, SCL);
    G(Wo, P+O_T4, P+O_T5, 128, 128, Np, 0, 1, 128, (long)Np*128, 1, 128, (long)128*Np);
    BN(P+O_T5, nullptr, P+O_Y, P+O_MU, P+O_IS, 128, Np);
    G(Wf1, P+O_Y, P+O_F, 128, 512, Np, 0, 1, 128, (long)128*Np, Np, 1, (long)512*Np);
    BN(P+O_F, nullptr, P+O_F, P+O_MU, P+O_IS, 512, Np);
    G(Wf2, P+O_F, P+O_T6, 512, 128, Np, 0, 1, 512, (long)512*Np, Np, 1, (long)128*Np);
    BN(P+O_T6, P+O_Y, outb, P+O_MU, P+O_IS, 128, Np);
}

static void EDGE(const float* X, int Cin, const float* W, float* e, float* P, int* idx)
{
    KNN(X, Cin, NPTS, P, idx);
    wdiff_k<<<(128*Cin+255)/256, 256>>>(W, P+O_WD, 128, Cin);
    long XB = (long)Cin*NPTS;
    G(X, P+O_WD, P+O_T1, Cin, NPTS, 128, XB, NPTS, 1, 0, 1, Cin, (long)NPTS*128);     // Ut
    G(X, W+Cin,  P+O_T2, Cin, NPTS, 128, XB, NPTS, 1, 0, 1, 2*Cin, (long)NPTS*128);   // Vt
    edge_assemble<<<BB*NPTS, 128>>>(P+O_T1, P+O_T2, idx, P+O_T3, P+O_T4, P+O_T5, NPTS);
    stats_sums<<<128, 256>>>(P+O_T4, P+O_T5, P+O_MU, P+O_IS, 128, NPTS, (long)BB*NPTS*KNB);
    long tot = (long)BB*128*NPTS;
    bn_leaky<<<(int)((tot+255)/256), 256>>>(P+O_T3, nullptr, e, P+O_MU, P+O_IS, 128, NPTS, tot);
}

extern "C" void kernel_launch(void* const* d_in, const int* in_sizes, int n_in,
                              void* d_out, int out_size)
{
    (void)in_sizes; (void)n_in; (void)out_size;
    static float* P = nullptr; static int* IP = nullptr;
    if (!P) {
        cudaGetSymbolAddress((void**)&P, g_pool);
        cudaGetSymbolAddress((void**)&IP, g_ipool);
    }
    const float* x   = (const float*)d_in[0];
    const float* cat = (const float*)d_in[1];
    const float* We0 = (const float*)d_in[2];
    const float* We1 = (const float*)d_in[3];
    const float* W[3][6];
    for (int l = 0; l < 3; l++)
        for (int j = 0; j < 6; j++) W[l][j] = (const float*)d_in[4 + l*6 + j];
    const float* Wdq = (const float*)d_in[22];
    const float* Wdk = (const float*)d_in[23];
    const float* Wuq = (const float*)d_in[24];
    const float* Wuk = (const float*)d_in[25];
    const float* Wuv = (const float*)d_in[26];
    const float* Wc  = (const float*)d_in[27];
    const float* Wc1 = (const float*)d_in[28];
    const float* Wc2 = (const float*)d_in[29];
    const float* Wc3 = (const float*)d_in[30];
    const float* Wc4 = (const float*)d_in[31];
    float* out = (float*)d_out;
    const int Np = NPTS, Mm = MSEL;
    int* sel = IP + SELOFF;

    // ---- encoder ----
    EDGE(x, 3, We0, P+O_E0, P, IP);
    EDGE(P+O_E0, 128, We1, P+O_E1, P, IP);
    {
        long tot = (long)BB*256*Np;
        concat2_k<<<(int)((tot+255)/256), 256>>>(P+O_E0, P+O_E1, P+O_H, 128, Np, tot);
    }
    N2P(P+O_H, 256, Np, W[0][0], W[0][1], W[0][2], W[0][3], W[0][4], W[0][5], P+O_HF, P, IP);

    // ---- down_global: select top-M points ----
    G(Wdq, P+O_HF, P+O_T1, 128, 128, Np, 0, 1, 128, (long)128*Np, Np, 1, (long)128*Np);
    G(Wdk, P+O_HF, P+O_T2, 128, 128, Np, 0, 1, 128, (long)128*Np, Np, 1, (long)128*Np);
    G(P+O_T1, P+O_T2, P+O_S, 128, Np, Np, (long)128*Np, Np, 1, (long)128*Np, Np, 1, (long)Np*Np);
    row_stats<<<BB*Np, 256>>>(P+O_S, P+O_RM, P+O_RI, Np, SCL);
    col_score<<<dim3(Np/256, BB), 256>>>(P+O_S, P+O_RM, P+O_RI, P+O_SC, Np, SCL);
    topM_select<<<BB, 256, Np*4>>>(P+O_SC, sel, Np, Mm);
    {
        long tot = (long)BB*128*Mm;
        gather_cols<<<(int)((tot+255)/256), 256>>>(P+O_HF, sel, P+O_HD, 128, Np, Mm, tot);
    }
    N2P(P+O_HD, 128, Mm, W[1][0], W[1][1], W[1][2], W[1][3], W[1][4], W[1][5], P+O_HD2, P, IP);

    // ---- up_cross ----
    G(Wuq, P+O_HF,  P+O_T1, 128, 128, Np, 0, 1, 128, (long)128*Np, Np, 1, (long)128*Np);
    G(Wuk, P+O_HD2, P+O_T2, 128, 128, Mm, 0, 1, 128, (long)128*Mm, Mm, 1, (long)128*Mm);
    G(Wuv, P+O_HD2, P+O_T3, 128, 128, Mm, 0, 1, 128, (long)128*Mm, Mm, 1, (long)128*Mm);
    G(P+O_T1, P+O_T2, P+O_S, 128, Np, Mm, (long)128*Np, Np, 1, (long)128*Mm, Mm, 1, (long)Np*Mm);
    softmax_rows<<<BB*Np, 256, Mm*4>>>(P+O_S, Mm, SCL);
    G(P+O_T3, P+O_S, P+O_T4, Mm, 128, Np, (long)128*Mm, 1, Mm, (long)Np*Mm, 1, Mm, (long)128*Np);
    add2_k<<<(int)((NT+255)/256), 256>>>(P+O_HF, P+O_T4, P+O_HU, NT);
    N2P(P+O_HU, 128, Np, W[2][0], W[2][1], W[2][2], W[2][3], W[2][4], W[2][5], P+O_XT, P, IP);

    // ---- head ----
    G(Wc, P+O_XT, P+O_B1, 128, 1024, Np, 0, 1, 128, (long)128*Np, Np, 1, (long)1024*Np);
    BN(P+O_B1, nullptr, P+O_B1, P+O_MU, P+O_IS, 1024, Np);
    chan_maxmean<<<BB*1024, 256>>>(P+O_B1, P+O_GV);
    cid_k<<<1, 64>>>(Wc1, cat, P+O_GV);
    cvec_k<<<BB*1024/8, 256>>>(Wc2, P+O_GV, P+O_CV);
    G(Wc2+2112, P+O_XT, P+O_B2, 128, 1024, Np, 0, 1, 2240, (long)128*Np, Np, 1, (long)1024*Np);
    {
        long tot = (long)BB*1024*Np;
        add_bias_bo<<<(int)((tot+255)/256), 256>>>(P+O_B2, P+O_CV, Np, tot);
    }
    BN(P+O_B2, nullptr, P+O_B2, P+O_MU, P+O_IS, 1024, Np);
    G(Wc3, P+O_B2, P+O_B1, 1024, 256, Np, 0, 1, 1024, (long)1024*Np, Np, 1, (long)256*Np);
    BN(P+O_B1, nullptr, P+O_B1, P+O_MU, P+O_IS, 256, Np);
    G(Wc4, P+O_B1, out, 256, 50, Np, 0, 1, 256, (long)256*Np, Np, 1, (long)50*Np);
}

// round 4
// speedup vs baseline: 1.0943x; 1.0943x over previous
#include <cuda_runtime.h>
#include <math.h>
#include <float.h>

#define BB   8
#define NPTS 2048
#define KNB  32
#define MSEL 1024
#define SCL  0.08838834764831845f

// ---------------- scratch pool (static device memory, no allocs) ----------
static constexpr long NT    = (long)BB*128*NPTS;              // 2,097,152
static constexpr long O_S   = 0;                               // 8*2048*2048
static constexpr long O_B1  = O_S  + (long)BB*NPTS*NPTS;
static constexpr long O_B2  = O_B1 + (long)BB*1024*NPTS;
static constexpr long O_F   = O_B2 + (long)BB*1024*NPTS;       // 512ch
static constexpr long O_E0  = O_F  + (long)BB*512*NPTS;
static constexpr long O_E1  = O_E0 + NT;
static constexpr long O_H   = O_E1 + NT;                       // 256ch
static constexpr long O_HF  = O_H  + 2*NT;
static constexpr long O_HU  = O_HF + NT;
static constexpr long O_T1  = O_HU + NT;
static constexpr long O_T2  = O_T1 + NT;
static constexpr long O_T3  = O_T2 + NT;
static constexpr long O_T4  = O_T3 + NT;
static constexpr long O_T5  = O_T4 + NT;
static constexpr long O_T6  = O_T5 + NT;
static constexpr long O_Y   = O_T6 + NT;
static constexpr long O_XT  = O_Y  + NT;
static constexpr long O_HD  = O_XT + NT;                       // 8*128*1024
static constexpr long O_HD2 = O_HD + (long)BB*128*MSEL;
static constexpr long O_SQ  = O_HD2+ (long)BB*128*MSEL;
static constexpr long O_RM  = O_SQ + BB*NPTS;
static constexpr long O_RI  = O_RM + BB*NPTS;
static constexpr long O_SC  = O_RI + BB*NPTS;
static constexpr long O_GV  = O_SC + BB*NPTS;                  // 8*2112
static constexpr long O_CV  = O_GV + BB*2112;                  // 8*1024
static constexpr long O_MU  = O_CV + BB*1024;
static constexpr long O_IS  = O_MU + 1024;
// transposed-weight region
static constexpr long LSZ   = 245760;                          // per n2p layer
static constexpr long O_WT  = O_IS + 1024;                     // 3 layers
static constexpr long O_WE  = O_WT + 3*LSZ;                    // 4 x 16384 edge
static constexpr long O_W5  = O_WE + 4*16384;                  // 5 x 16384
static constexpr long O_WC  = O_W5 + 5*16384;                  // 131072
static constexpr long O_WC2 = O_WC + 131072;                   // 131072
static constexpr long O_WC3 = O_WC2+ 131072;                   // 262144
static constexpr long O_WC4 = O_WC3+ 262144;                   // 12800
static constexpr long POOLSZ= O_WC4 + 12800;

__device__ __align__(128) float g_pool[POOLSZ];
__device__ int g_ipool[(long)BB*NPTS*KNB + BB*MSEL];
static constexpr long SELOFF = (long)BB*NPTS*KNB;

// ---------------- 128x128x8 strided-batch TN SGEMM ------------------------
// C[b,i,j] = sum_k A[b*abs + k*ask + i*asi] * B[b*bbs + k*bsk + j*bsj]
// REQUIRES: J % 4 == 0 (float4 stores). asi/bsj should be 1 for coalescing.
__global__ __launch_bounds__(256) void gemm_tn(
    const float* __restrict__ A, const float* __restrict__ B,
    float* __restrict__ C, int Kd, int I, int J,
    long abs_, long ask, long asi,
    long bbs, long bsk, long bsj, long cbs)
{
    __shared__ float As[8][128];
    __shared__ float Bs[8][128];
    const int tid = threadIdx.x;
    const int tx = tid & 15, ty = tid >> 4;
    A += (long)blockIdx.z * abs_; B += (long)blockIdx.z * bbs;
    C += (long)blockIdx.z * cbs;
    const int i0 = blockIdx.y * 128, j0 = blockIdx.x * 128;
    const int li = tid & 127;
    const int k00 = tid >> 7;            // 0 or 1
    const int ia = i0 + li, jb = j0 + li;
    float acc[8][8] = {};
    float pa[4], pb[4];
#pragma unroll
    for (int u = 0; u < 4; u++) {
        int kk = k00 + u*2;
        pa[u] = (ia < I && kk < Kd) ? A[(long)kk*ask + (long)ia*asi] : 0.f;
        pb[u] = (jb < J && kk < Kd) ? B[(long)kk*bsk + (long)jb*bsj] : 0.f;
    }
    for (int k0 = 0; k0 < Kd; k0 += 8) {
#pragma unroll
        for (int u = 0; u < 4; u++) {
            As[k00 + u*2][li] = pa[u];
            Bs[k00 + u*2][li] = pb[u];
        }
        __syncthreads();
        int kn = k0 + 8;
        if (kn < Kd) {
#pragma unroll
            for (int u = 0; u < 4; u++) {
                int kk = kn + k00 + u*2;
                pa[u] = (ia < I && kk < Kd) ? A[(long)kk*ask + (long)ia*asi] : 0.f;
                pb[u] = (jb < J && kk < Kd) ? B[(long)kk*bsk + (long)jb*bsj] : 0.f;
            }
        }
#pragma unroll
        for (int kk = 0; kk < 8; kk++) {
            float4 a0 = *(const float4*)&As[kk][ty*8];
            float4 a1 = *(const float4*)&As[kk][ty*8 + 4];
            float4 b0 = *(const float4*)&Bs[kk][tx*8];
            float4 b1 = *(const float4*)&Bs[kk][tx*8 + 4];
            float ar[8] = {a0.x,a0.y,a0.z,a0.w,a1.x,a1.y,a1.z,a1.w};
            float br[8] = {b0.x,b0.y,b0.z,b0.w,b1.x,b1.y,b1.z,b1.w};
#pragma unroll
            for (int a = 0; a < 8; a++)
#pragma unroll
                for (int b2 = 0; b2 < 8; b2++) acc[a][b2] += ar[a]*br[b2];
        }
        __syncthreads();
    }
#pragma unroll
    for (int a = 0; a < 8; a++) {
        int i = i0 + ty*8 + a;
        if (i >= I) continue;
        int j = j0 + tx*8;
        if (j + 7 < J) {
            *(float4*)&C[(long)i*J + j]     = make_float4(acc[a][0],acc[a][1],acc[a][2],acc[a][3]);
            *(float4*)&C[(long)i*J + j + 4] = make_float4(acc[a][4],acc[a][5],acc[a][6],acc[a][7]);
        } else {
#pragma unroll
            for (int b2 = 0; b2 < 8; b2++)
                if (j + b2 < J) C[(long)i*J + j + b2] = acc[a][b2];
        }
    }
}

// WT[c*O + o] = W[o*ld + c0 + c]
__global__ void wt_k(const float* __restrict__ W, float* __restrict__ WT,
                     int O, int Cin, int ld, int c0)
{
    int i = blockIdx.x*256 + threadIdx.x;
    if (i >= O*Cin) return;
    int c = i / O, o = i % O;
    WT[i] = W[(long)o*ld + c0 + c];
}

// transposed edge weight split: WdT[c*128+o] = W1-W2, W2T[c*128+o] = W2
__global__ void wdiff_k(const float* __restrict__ W, float* __restrict__ WdT,
                        float* __restrict__ W2T, int Cin)
{
    int i = blockIdx.x*256 + threadIdx.x;
    if (i >= Cin*128) return;
    int c = i / 128, o = i % 128;
    float w1 = W[(long)o*2*Cin + c], w2 = W[(long)o*2*Cin + Cin + c];
    WdT[i] = w1 - w2; W2T[i] = w2;
}

// (b,n,c) -> (b,c,n)
__global__ void transpose_nc(const float* __restrict__ X, float* __restrict__ Y,
                             int C, int Np)
{
    __shared__ float t[32][33];
    int b = blockIdx.z;
    int n0 = blockIdx.x*32, c0 = blockIdx.y*32;
    for (int yy = threadIdx.y; yy < 32; yy += 8) {
        int n = n0 + yy, c = c0 + threadIdx.x;
        if (n < Np && c < C) t[yy][threadIdx.x] = X[((long)b*Np + n)*C + c];
    }
    __syncthreads();
    for (int yy = threadIdx.y; yy < 32; yy += 8) {
        int c = c0 + yy, n = n0 + threadIdx.x;
        if (n < Np && c < C) Y[((long)b*C + c)*Np + n] = t[threadIdx.x][yy];
    }
}

// sq[b,n] = sum_c X[b,c,n]^2
__global__ void colnorm_k(const float* __restrict__ X, float* __restrict__ sq,
                          int C, int Np)
{
    int i = blockIdx.x*blockDim.x + threadIdx.x;
    if (i >= BB*Np) return;
    int b = i/Np, n = i%Np;
    const float* p = X + (long)b*C*Np + n;
    float s = 0.f;
    for (int c = 0; c < C; c++) { float v = p[(long)c*Np]; s += v*v; }
    sq[i] = s;
}

// per-row top-32 smallest distances, tie-break lower index (matches jax)
__global__ void knn_topk(const float* __restrict__ S, const float* __restrict__ sq,
                         int* __restrict__ idx, int Np)
{
    extern __shared__ float sd[];
    __shared__ float wv[8]; __shared__ int wi[8];
    int bn = blockIdx.x, b = bn/Np, n = bn%Np, tid = threadIdx.x;
    const float* Srow = S + ((long)b*Np + n)*Np;
    float sn = sq[(long)b*Np + n];
    for (int m = tid; m < Np; m += 256)
        sd[m] = sn - 2.f*Srow[m] + sq[(long)b*Np + m];
    __syncthreads();
    int lane = tid & 31, w = tid >> 5;
    for (int k = 0; k < KNB; k++) {
        float bv = FLT_MAX; int bi = 0x7fffffff;
        for (int m = tid; m < Np; m += 256) {
            float v = sd[m];
            if (v < bv) { bv = v; bi = m; }
        }
#pragma unroll
        for (int o = 16; o > 0; o >>= 1) {
            float ov = __shfl_down_sync(0xffffffffu, bv, o);
            int   oi = __shfl_down_sync(0xffffffffu, bi, o);
            if (ov < bv || (ov == bv && oi < bi)) { bv = ov; bi = oi; }
        }
        if (lane == 0) { wv[w] = bv; wi[w] = bi; }
        __syncthreads();
        if (tid == 0) {
            float rv = wv[0]; int ri = wi[0];
            for (int j = 1; j < 8; j++)
                if (wv[j] < rv || (wv[j] == rv && wi[j] < ri)) { rv = wv[j]; ri = wi[j]; }
            idx[((long)b*Np + n)*KNB + k] = ri;
            sd[ri] = FLT_MAX;
        }
        __syncthreads();
    }
}

// Ut,Vt in (b,n,o); outputs max/sum/sumsq over k in (b,o,n)
__global__ void edge_assemble(const float* __restrict__ Ut, const float* __restrict__ Vt,
                              const int* __restrict__ idx,
                              float* __restrict__ Ym, float* __restrict__ Ys,
                              float* __restrict__ Yq, int Np)
{
    int bn = blockIdx.x, b = bn/Np, o = threadIdx.x;
    float u = Ut[(long)bn*128 + o];
    const int* ip = idx + (long)bn*KNB;
    const float* vb = Vt + (long)b*Np*128;
    float mx = -FLT_MAX, s = 0.f, q = 0.f;
#pragma unroll 4
    for (int k = 0; k < KNB; k++) {
        int m = ip[k];
        float v = u + vb[(long)m*128 + o];
        mx = fmaxf(mx, v); s += v; q += v*v;
    }
    int n = bn % Np;
    long off = ((long)b*128 + o)*Np + n;
    Ym[off] = mx; Ys[off] = s; Yq[off] = q;
}

__global__ void stats_sums(const float* __restrict__ S1, const float* __restrict__ S2,
                           float* __restrict__ mu, float* __restrict__ is,
                           int O, int Np, long cnt)
{
    int o = blockIdx.x, tid = threadIdx.x;
    double s = 0, q = 0;
    for (int b = 0; b < BB; b++) {
        const float* p1 = S1 + ((long)b*O + o)*Np;
        const float* p2 = S2 + ((long)b*O + o)*Np;
        for (int n = tid; n < Np; n += 256) { s += p1[n]; q += p2[n]; }
    }
    __shared__ double ss[256], qq[256];
    ss[tid] = s; qq[tid] = q; __syncthreads();
    for (int st = 128; st > 0; st >>= 1) {
        if (tid < st) { ss[tid] += ss[tid+st]; qq[tid] += qq[tid+st]; }
        __syncthreads();
    }
    if (tid == 0) {
        double m = ss[0]/(double)cnt, v = qq[0]/(double)cnt - m*m;
        mu[o] = (float)m; is[o] = (float)(1.0/sqrt(v + 1e-5));
    }
}

__global__ void stats_tensor(const float* __restrict__ X, float* __restrict__ mu,
                             float* __restrict__ is, int O, int Np, long cnt)
{
    int o = blockIdx.x, tid = threadIdx.x;
    double s = 0, q = 0;
    for (int b = 0; b < BB; b++) {
        const float* p = X + ((long)b*O + o)*Np;
        for (int n = tid; n < Np; n += 256) { double v = p[n]; s += v; q += v*v; }
    }
    __shared__ double ss[256], qq[256];
    ss[tid] = s; qq[tid] = q; __syncthreads();
    for (int st = 128; st > 0; st >>= 1) {
        if (tid < st) { ss[tid] += ss[tid+st]; qq[tid] += qq[tid+st]; }
        __syncthreads();
    }
    if (tid == 0) {
        double m = ss[0]/(double)cnt, v = qq[0]/(double)cnt - m*m;
        mu[o] = (float)m; is[o] = (float)(1.0/sqrt(v + 1e-5));
    }
}

__global__ void bn_leaky(const float* __restrict__ X, const float* __restrict__ res,
                         float* __restrict__ Y, const float* __restrict__ mu,
                         const float* __restrict__ is, int O, int Np, long total)
{
    long i = (long)blockIdx.x*blockDim.x + threadIdx.x;
    if (i >= total) return;
    int o = (int)((i / Np) % O);
    float v = (X[i] - mu[o]) * is[o];
    v = v > 0.f ? v : 0.2f*v;
    Y[i] = res ? res[i] + v : v;
}

__global__ void concat2_k(const float* __restrict__ A, const float* __restrict__ B,
                          float* __restrict__ H, int C, int Np, long total)
{
    long i = (long)blockIdx.x*blockDim.x + threadIdx.x;
    if (i >= total) return;
    long per = (long)2*C*Np;
    int b = (int)(i/per); long r = i % per;
    int c = (int)(r/Np), n = (int)(r%Np);
    H[i] = (c < C) ? A[((long)b*C + c)*Np + n] : B[((long)b*C + c - C)*Np + n];
}

// warp-per-query local attention; qt/kt/vt/out in (b,n,c), c=128, K=32
__global__ void n2p_core(const float* __restrict__ qt, const float* __restrict__ kt,
                         const float* __restrict__ vt, const int* __restrict__ idx,
                         float* __restrict__ outt, int Np, float scale)
{
    __shared__ float qsh[4][128];
    int warp = threadIdx.x >> 5, lane = threadIdx.x & 31;
    long bn = (long)blockIdx.x*4 + warp;
    int b = (int)(bn/Np), n = (int)(bn%Np);
    const float* qp = qt + ((long)b*Np + n)*128;
    for (int c = lane; c < 128; c += 32) qsh[warp][c] = qp[c];
    __syncwarp();
    int m = idx[((long)b*Np + n)*KNB + lane];
    const float4* krow = (const float4*)(kt + ((long)b*Np + m)*128);
    float dot = 0.f;
#pragma unroll
    for (int c4 = 0; c4 < 32; c4++) {
        float4 kv = krow[c4];
        dot += qsh[warp][c4*4+0]*kv.x + qsh[warp][c4*4+1]*kv.y +
               qsh[warp][c4*4+2]*kv.z + qsh[warp][c4*4+3]*kv.w;
    }
    float logit = dot * scale, mx = logit;
#pragma unroll
    for (int o = 16; o > 0; o >>= 1) mx = fmaxf(mx, __shfl_xor_sync(0xffffffffu, mx, o));
    float e = __expf(logit - mx), sum = e;
#pragma unroll
    for (int o = 16; o > 0; o >>= 1) sum += __shfl_xor_sync(0xffffffffu, sum, o);
    float a = e / sum;
    const float* vbase = vt + (long)b*Np*128;
    float acc[4] = {0.f, 0.f, 0.f, 0.f};
#pragma unroll
    for (int k = 0; k < KNB; k++) {
        float ak = __shfl_sync(0xffffffffu, a, k);
        int  mk = __shfl_sync(0xffffffffu, m, k);
        const float* vr = vbase + (long)mk*128;
#pragma unroll
        for (int cb = 0; cb < 4; cb++) acc[cb] += ak * vr[cb*32 + lane];
    }
    float* op = outt + ((long)b*Np + n)*128;
#pragma unroll
    for (int cb = 0; cb < 4; cb++) op[cb*32 + lane] = acc[cb];
}

// pass 1: rmax[bn] = scale * max_m S[bn, m]
__global__ void row_max(const float* __restrict__ S, float* __restrict__ rmax,
                        int Np, float scale)
{
    __shared__ float red[256];
    long bn = blockIdx.x; int tid = threadIdx.x;
    const float* row = S + bn*Np;
    float mx = -FLT_MAX;
    for (int m = tid; m < Np; m += 256) mx = fmaxf(mx, row[m]);
    red[tid] = mx; __syncthreads();
    for (int s = 128; s > 0; s >>= 1) {
        if (tid < s) red[tid] = fmaxf(red[tid], red[tid+s]);
        __syncthreads();
    }
    if (tid == 0) rmax[bn] = red[0]*scale;
}

// pass 2: S <- exp(S*scale - rmax), rinv[bn] = 1/rowsum
__global__ void row_exp(float* __restrict__ S, const float* __restrict__ rmax,
                        float* __restrict__ rinv, int Np, float scale)
{
    __shared__ float red[256];
    long bn = blockIdx.x; int tid = threadIdx.x;
    float* row = S + bn*Np;
    float M = rmax[bn], sum = 0.f;
    for (int m = tid; m < Np; m += 256) {
        float e = __expf(row[m]*scale - M);
        row[m] = e; sum += e;
    }
    red[tid] = sum; __syncthreads();
    for (int s = 128; s > 0; s >>= 1) {
        if (tid < s) red[tid] += red[tid+s];
        __syncthreads();
    }
    if (tid == 0) rinv[bn] = 1.f/red[0];
}

// pass 3: score[b,m] = (1/Np) * sum_n P[n,m] * rinv[n]   (no exp)
__global__ void col_score(const float* __restrict__ S, const float* __restrict__ rinv,
                          float* __restrict__ score, int Np)
{
    __shared__ float rsh[NPTS];
    int b = blockIdx.y;
    int m = blockIdx.x*256 + threadIdx.x;
    for (int n = threadIdx.x; n < Np; n += 256) rsh[n] = rinv[(long)b*Np + n];
    __syncthreads();
    if (m >= Np) return;
    const float* Sb = S + (long)b*Np*Np;
    float acc = 0.f;
#pragma unroll 4
    for (int n = 0; n < Np; n++) acc += Sb[(long)n*Np + m]*rsh[n];
    score[(long)b*Np + m] = acc * (1.f/Np);
}

__global__ void topM_select(const float* __restrict__ score, int* __restrict__ sel,
                            int Np, int M)
{
    extern __shared__ float sc[];
    int b = blockIdx.x, tid = threadIdx.x;
    for (int m = tid; m < Np; m += 256) sc[m] = score[(long)b*Np + m];
    __syncthreads();
    for (int m = tid; m < Np; m += 256) {
        float v = sc[m];
        int r = 0;
        for (int j = 0; j < Np; j++) {
            float u = sc[j];
            r += (u > v) || (u == v && j < m);
        }
        if (r < M) sel[b*M + r] = m;
    }
}

__global__ void gather_cols(const float* __restrict__ X, const int* __restrict__ sel,
                            float* __restrict__ Y, int C, int Nsrc, int Mdst, long total)
{
    long i = (long)blockIdx.x*blockDim.x + threadIdx.x;
    if (i >= total) return;
    long per = (long)C*Mdst;
    int b = (int)(i/per); long r = i % per;
    int c = (int)(r/Mdst), j = (int)(r%Mdst);
    Y[i] = X[((long)b*C + c)*Nsrc + sel[b*Mdst + j]];
}

__global__ void softmax_rows(float* __restrict__ S, int cols, float scale)
{
    extern __shared__ float buf[];
    __shared__ float red[256];
    long row = blockIdx.x;
    int tid = threadIdx.x;
    float* p = S + row*cols;
    float mx = -FLT_MAX;
    for (int j = tid; j < cols; j += 256) { float v = p[j]*scale; buf[j] = v; mx = fmaxf(mx, v); }
    red[tid] = mx; __syncthreads();
    for (int s = 128; s > 0; s >>= 1) {
        if (tid < s) red[tid] = fmaxf(red[tid], red[tid+s]);
        __syncthreads();
    }
    float M = red[0]; __syncthreads();
    float sum = 0.f;
    for (int j = tid; j < cols; j += 256) { float e = __expf(buf[j]-M); buf[j] = e; sum += e; }
    red[tid] = sum; __syncthreads();
    for (int s = 128; s > 0; s >>= 1) {
        if (tid < s) red[tid] += red[tid+s];
        __syncthreads();
    }
    float inv = 1.f/red[0];
    for (int j = tid; j < cols; j += 256) p[j] = buf[j]*inv;
}

__global__ void add2_k(const float* __restrict__ A, const float* __restrict__ B,
                       float* __restrict__ Y, long total)
{
    long i = (long)blockIdx.x*blockDim.x + threadIdx.x;
    if (i < total) Y[i] = A[i] + B[i];
}

__global__ void chan_maxmean(const float* __restrict__ X, float* __restrict__ gvec)
{
    __shared__ float rm[256], rs[256];
    int bo = blockIdx.x, b = bo/1024, o = bo%1024, tid = threadIdx.x;
    const float* p = X + (long)bo*NPTS;
    float mx = -FLT_MAX, s = 0.f;
    for (int n = tid; n < NPTS; n += 256) { float v = p[n]; mx = fmaxf(mx, v); s += v; }
    rm[tid] = mx; rs[tid] = s; __syncthreads();
    for (int st = 128; st > 0; st >>= 1) {
        if (tid < st) { rm[tid] = fmaxf(rm[tid], rm[tid+st]); rs[tid] += rs[tid+st]; }
        __syncthreads();
    }
    if (tid == 0) {
        gvec[(long)b*2112 + o]        = rm[0];
        gvec[(long)b*2112 + 1024 + o] = rs[0]*(1.f/NPTS);
    }
}

__global__ void cid_k(const float* __restrict__ W, const float* __restrict__ cat,
                      float* __restrict__ gvec)
{
    int o = threadIdx.x;
    if (o >= 64) return;
    float y[8]; double s = 0, q = 0;
    for (int b = 0; b < 8; b++) {
        float a = 0.f;
        for (int c = 0; c < 16; c++) a += W[o*16+c]*cat[b*16+c];
        y[b] = a; s += a; q += (double)a*a;
    }
    double m = s/8.0, v = q/8.0 - m*m;
    float is = (float)(1.0/sqrt(v + 1e-5));
    for (int b = 0; b < 8; b++) {
        float t = (y[b] - (float)m)*is;
        gvec[(long)b*2112 + 2048 + o] = t > 0.f ? t : 0.2f*t;
    }
}

__global__ void cvec_k(const float* __restrict__ Wc2, const float* __restrict__ gvec,
                       float* __restrict__ cvec)
{
    long gid = (long)blockIdx.x*256 + threadIdx.x;
    int warp = (int)(gid >> 5), lane = (int)(gid & 31);
    if (warp >= BB*1024) return;
    int b = warp/1024, o = warp%1024;
    const float* wr = Wc2 + (long)o*2240;
    const float* gv = gvec + (long)b*2112;
    float s = 0.f;
    for (int j = lane; j < 2112; j += 32) s += wr[j]*gv[j];
#pragma unroll
    for (int t = 16; t > 0; t >>= 1) s += __shfl_down_sync(0xffffffffu, s, t);
    if (lane == 0) cvec[warp] = s;
}

__global__ void add_bias_bo(float* __restrict__ X, const float* __restrict__ cst,
                            int Np, long total)
{
    long i = (long)blockIdx.x*blockDim.x + threadIdx.x;
    if (i < total) X[i] += cst[i/Np];
}

// ---------------- host orchestration --------------------------------------
static void G(const float* A, const float* B, float* C, int Kd, int I, int J,
              long abs_, long ask, long asi, long bbs, long bsk, long bsj, long cbs)
{
    dim3 grid((J+127)/128, (I+127)/128, BB);
    gemm_tn<<<grid, 256>>>(A, B, C, Kd, I, J, abs_, ask, asi, bbs, bsk, bsj, cbs);
}

static void BN(const float* X, const float* res, float* Y, float* mu, float* is,
               int O, int Np)
{
    stats_tensor<<<O, 256>>>(X, mu, is, O, Np, (long)BB*Np);
    long tot = (long)BB*O*Np;
    bn_leaky<<<(int)((tot+255)/256), 256>>>(X, res, Y, mu, is, O, Np, tot);
}

static void KNN(const float* X, int Cin, int Np, float* P, int* idx)
{
    colnorm_k<<<(BB*Np+255)/256, 256>>>(X, P+O_SQ, Cin, Np);
    G(X, X, P+O_S, Cin, Np, Np, (long)Cin*Np, Np, 1, (long)Cin*Np, Np, 1, (long)Np*Np);
    knn_topk<<<BB*Np, 256, Np*4>>>(P+O_S, P+O_SQ, idx, Np);
}

static void N2P(const float* X, int Cin, int Np, const float* WT,
                float* outb, float* P, int* idx)
{
    const float* WqT  = WT;
    const float* WkT  = WT + 32768;
    const float* WvT  = WT + 65536;
    const float* WoT  = WT + 98304;
    const float* Wf1T = WT + 114688;
    const float* Wf2T = WT + 180224;
    KNN(X, Cin, Np, P, idx);
    long XB = (long)Cin*Np;
    // q/k/v in (b,n,c):  C[n,o] = sum_c X[c,n] * WT[c,o]
    G(X, WqT, P+O_T1, Cin, Np, 128, XB, Np, 1, 0, 128, 1, (long)Np*128);
    G(X, WkT, P+O_T2, Cin, Np, 128, XB, Np, 1, 0, 128, 1, (long)Np*128);
    G(X, WvT, P+O_T3, Cin, Np, 128, XB, Np, 1, 0, 128, 1, (long)Np*128);
    n2p_core<<<BB*Np/4, 128>>>(P+O_T1, P+O_T2, P+O_T3, idx, P+O_T4, Np, SCL);
    transpose_nc<<<dim3((Np+31)/32, 4, BB), dim3(32,8)>>>(P+O_T4, P+O_T5, 128, Np);
    // Wo: (b,c,n) out:  C[o,n] = sum_c WoT[c,o] * T5[c,n]
    G(WoT, P+O_T5, P+O_T6, 128, 128, Np, 0, 128, 1, (long)128*Np, Np, 1, (long)128*Np);
    BN(P+O_T6, nullptr, P+O_Y, P+O_MU, P+O_IS, 128, Np);
    G(Wf1T, P+O_Y, P+O_F, 128, 512, Np, 0, 512, 1, (long)128*Np, Np, 1, (long)512*Np);
    BN(P+O_F, nullptr, P+O_F, P+O_MU, P+O_IS, 512, Np);
    G(Wf2T, P+O_F, P+O_T6, 512, 128, Np, 0, 128, 1, (long)512*Np, Np, 1, (long)128*Np);
    BN(P+O_T6, P+O_Y, outb, P+O_MU, P+O_IS, 128, Np);
}

static void EDGE(const float* X, int Cin, const float* W, float* wdT, float* w2T,
                 float* e, float* P, int* idx)
{
    KNN(X, Cin, NPTS, P, idx);
    wdiff_k<<<(Cin*128+255)/256, 256>>>(W, wdT, w2T, Cin);
    long XB = (long)Cin*NPTS;
    G(X, wdT, P+O_T1, Cin, NPTS, 128, XB, NPTS, 1, 0, 128, 1, (long)NPTS*128);  // Ut (b,n,o)
    G(X, w2T, P+O_T2, Cin, NPTS, 128, XB, NPTS, 1, 0, 128, 1, (long)NPTS*128);  // Vt (b,n,o)
    edge_assemble<<<BB*NPTS, 128>>>(P+O_T1, P+O_T2, idx, P+O_T3, P+O_T4, P+O_T5, NPTS);
    stats_sums<<<128, 256>>>(P+O_T4, P+O_T5, P+O_MU, P+O_IS, 128, NPTS, (long)BB*NPTS*KNB);
    long tot = (long)BB*128*NPTS;
    bn_leaky<<<(int)((tot+255)/256), 256>>>(P+O_T3, nullptr, e, P+O_MU, P+O_IS, 128, NPTS, tot);
}

extern "C" void kernel_launch(void* const* d_in, const int* in_sizes, int n_in,
                              void* d_out, int out_size)
{
    (void)in_sizes; (void)n_in; (void)out_size;
    static float* P = nullptr; static int* IP = nullptr;
    if (!P) {
        cudaGetSymbolAddress((void**)&P, g_pool);
        cudaGetSymbolAddress((void**)&IP, g_ipool);
    }
    const float* x   = (const float*)d_in[0];
    const float* cat = (const float*)d_in[1];
    const float* We0 = (const float*)d_in[2];
    const float* We1 = (const float*)d_in[3];
    const float* W[3][6];
    for (int l = 0; l < 3; l++)
        for (int j = 0; j < 6; j++) W[l][j] = (const float*)d_in[4 + l*6 + j];
    const float* Wdq = (const float*)d_in[22];
    const float* Wdk = (const float*)d_in[23];
    const float* Wuq = (const float*)d_in[24];
    const float* Wuk = (const float*)d_in[25];
    const float* Wuv = (const float*)d_in[26];
    const float* Wc  = (const float*)d_in[27];
    const float* Wc1 = (const float*)d_in[28];
    const float* Wc2 = (const float*)d_in[29];
    const float* Wc3 = (const float*)d_in[30];
    const float* Wc4 = (const float*)d_in[31];
    float* out = (float*)d_out;
    const int Np = NPTS, Mm = MSEL;
    int* sel = IP + SELOFF;

    // ---- transpose all weights once per launch ----
    int cins[3] = {256, 128, 128};
    for (int l = 0; l < 3; l++) {
        float* base = P + O_WT + (long)l*LSZ;
        int ci = cins[l];
        wt_k<<<(128*ci+255)/256, 256>>>(W[l][0], base,          128, ci, ci, 0);
        wt_k<<<(128*ci+255)/256, 256>>>(W[l][1], base + 32768,  128, ci, ci, 0);
        wt_k<<<(128*ci+255)/256, 256>>>(W[l][2], base + 65536,  128, ci, ci, 0);
        wt_k<<<(128*128+255)/256, 256>>>(W[l][3], base + 98304, 128, 128, 128, 0);
        wt_k<<<(512*128+255)/256, 256>>>(W[l][4], base + 114688, 512, 128, 128, 0);
        wt_k<<<(128*512+255)/256, 256>>>(W[l][5], base + 180224, 128, 512, 512, 0);
    }
    wt_k<<<(128*128+255)/256, 256>>>(Wdq, P+O_W5,          128, 128, 128, 0);
    wt_k<<<(128*128+255)/256, 256>>>(Wdk, P+O_W5+16384,    128, 128, 128, 0);
    wt_k<<<(128*128+255)/256, 256>>>(Wuq, P+O_W5+32768,    128, 128, 128, 0);
    wt_k<<<(128*128+255)/256, 256>>>(Wuk, P+O_W5+49152,    128, 128, 128, 0);
    wt_k<<<(128*128+255)/256, 256>>>(Wuv, P+O_W5+65536,    128, 128, 128, 0);
    wt_k<<<(1024*128+255)/256, 256>>>(Wc,  P+O_WC,  1024, 128, 128, 0);
    wt_k<<<(1024*128+255)/256, 256>>>(Wc2, P+O_WC2, 1024, 128, 2240, 2112);
    wt_k<<<(256*1024+255)/256, 256>>>(Wc3, P+O_WC3, 256, 1024, 1024, 0);
    wt_k<<<(50*256+255)/256, 256>>>(Wc4, P+O_WC4, 50, 256, 256, 0);

    // ---- encoder ----
    EDGE(x, 3, We0, P+O_WE, P+O_WE+16384, P+O_E0, P, IP);
    EDGE(P+O_E0, 128, We1, P+O_WE+32768, P+O_WE+49152, P+O_E1, P, IP);
    {
        long tot = (long)BB*256*Np;
        concat2_k<<<(int)((tot+255)/256), 256>>>(P+O_E0, P+O_E1, P+O_H, 128, Np, tot);
    }
    N2P(P+O_H, 256, Np, P+O_WT, P+O_HF, P, IP);

    // ---- down_global ----
    const float* WdqT = P+O_W5, *WdkT = P+O_W5+16384;
    const float* WuqT = P+O_W5+32768, *WukT = P+O_W5+49152, *WuvT = P+O_W5+65536;
    G(WdqT, P+O_HF, P+O_T1, 128, 128, Np, 0, 128, 1, (long)128*Np, Np, 1, (long)128*Np);
    G(WdkT, P+O_HF, P+O_T2, 128, 128, Np, 0, 128, 1, (long)128*Np, Np, 1, (long)128*Np);
    G(P+O_T1, P+O_T2, P+O_S, 128, Np, Np, (long)128*Np, Np, 1, (long)128*Np, Np, 1, (long)Np*Np);
    row_max<<<BB*Np, 256>>>(P+O_S, P+O_RM, Np, SCL);
    row_exp<<<BB*Np, 256>>>(P+O_S, P+O_RM, P+O_RI, Np, SCL);
    col_score<<<dim3(Np/256, BB), 256>>>(P+O_S, P+O_RI, P+O_SC, Np);
    topM_select<<<BB, 256, Np*4>>>(P+O_SC, sel, Np, Mm);
    {
        long tot = (long)BB*128*Mm;
        gather_cols<<<(int)((tot+255)/256), 256>>>(P+O_HF, sel, P+O_HD, 128, Np, Mm, tot);
    }
    N2P(P+O_HD, 128, Mm, P+O_WT+LSZ, P+O_HD2, P, IP);

    // ---- up_cross ----
    G(WuqT, P+O_HF,  P+O_T1, 128, 128, Np, 0, 128, 1, (long)128*Np, Np, 1, (long)128*Np);
    G(WukT, P+O_HD2, P+O_T2, 128, 128, Mm, 0, 128, 1, (long)128*Mm, Mm, 1, (long)128*Mm);
    G(P+O_T1, P+O_T2, P+O_S, 128, Np, Mm, (long)128*Np, Np, 1, (long)128*Mm, Mm, 1, (long)Np*Mm);
    softmax_rows<<<BB*Np, 256, Mm*4>>>(P+O_S, Mm, SCL);
    transpose_nc<<<dim3((Np+31)/32, (Mm+31)/32, BB), dim3(32,8)>>>(P+O_S, P+O_B1, Mm, Np); // St (b,m,n)
    // Vt (b,m,c):  C[m,c] = sum_c' HD2[c',m] * WuvT[c',c]
    G(P+O_HD2, WuvT, P+O_T3, 128, Mm, 128, (long)128*Mm, Mm, 1, 0, 128, 1, (long)Mm*128);
    // out (b,c,n): C[c,n] = sum_m Vt[m,c] * St[m,n]
    G(P+O_T3, P+O_B1, P+O_T4, Mm, 128, Np, (long)Mm*128, 128, 1, (long)Mm*Np, Np, 1, (long)128*Np);
    add2_k<<<(int)((NT+255)/256), 256>>>(P+O_HF, P+O_T4, P+O_HU, NT);
    N2P(P+O_HU, 128, Np, P+O_WT+2*LSZ, P+O_XT, P, IP);

    // ---- head ----
    G(P+O_WC, P+O_XT, P+O_B1, 128, 1024, Np, 0, 1024, 1, (long)128*Np, Np, 1, (long)1024*Np);
    BN(P+O_B1, nullptr, P+O_B1, P+O_MU, P+O_IS, 1024, Np);
    chan_maxmean<<<BB*1024, 256>>>(P+O_B1, P+O_GV);
    cid_k<<<1, 64>>>(Wc1, cat, P+O_GV);
    cvec_k<<<BB*1024/8, 256>>>(Wc2, P+O_GV, P+O_CV);
    G(P+O_WC2, P+O_XT, P+O_B2, 128, 1024, Np, 0, 1024, 1, (long)128*Np, Np, 1, (long)1024*Np);
    {
        long tot = (long)BB*1024*Np;
        add_bias_bo<<<(int)((tot+255)/256), 256>>>(P+O_B2, P+O_CV, Np, tot);
    }
    BN(P+O_B2, nullptr, P+O_B2, P+O_MU, P+O_IS, 1024, Np);
    G(P+O_WC3, P+O_B2, P+O_B1, 1024, 256, Np, 0, 256, 1, (long)1024*Np, Np, 1, (long)256*Np);
    BN(P+O_B1, nullptr, P+O_B1, P+O_MU, P+O_IS, 256, Np);
    G(P+O_WC4, P+O_B1, out, 256, 50, Np, 0, 50, 1, (long)256*Np, Np, 1, (long)50*Np);
}

// round 11
// speedup vs baseline: 1.1101x; 1.0144x over previous
#include <cuda_runtime.h>
#include <math.h>
#include <float.h>

#define BB   8
#define NPTS 2048
#define KNB  32
#define MSEL 1024
#define SCL  0.08838834764831845f

// ---------------- scratch pool (static device memory, no allocs) ----------
static constexpr long NT    = (long)BB*128*NPTS;              // 2,097,152
static constexpr long O_S   = 0;                               // 8*2048*2048
static constexpr long O_B1  = O_S  + (long)BB*NPTS*NPTS;
static constexpr long O_B2  = O_B1 + (long)BB*1024*NPTS;
static constexpr long O_F   = O_B2 + (long)BB*1024*NPTS;       // 512ch
static constexpr long O_E0  = O_F  + (long)BB*512*NPTS;
static constexpr long O_E1  = O_E0 + NT;
static constexpr long O_H   = O_E1 + NT;                       // 256ch
static constexpr long O_HF  = O_H  + 2*NT;
static constexpr long O_HU  = O_HF + NT;
static constexpr long O_T1  = O_HU + NT;
static constexpr long O_T2  = O_T1 + NT;
static constexpr long O_T3  = O_T2 + NT;
static constexpr long O_T4  = O_T3 + NT;
static constexpr long O_T5  = O_T4 + NT;
static constexpr long O_T6  = O_T5 + NT;
static constexpr long O_Y   = O_T6 + NT;
static constexpr long O_XT  = O_Y  + NT;
static constexpr long O_HD  = O_XT + NT;                       // 8*128*1024
static constexpr long O_HD2 = O_HD + (long)BB*128*MSEL;
static constexpr long O_SQ  = O_HD2+ (long)BB*128*MSEL;
static constexpr long O_RM  = O_SQ + BB*NPTS;
static constexpr long O_RI  = O_RM + BB*NPTS;
static constexpr long O_SC  = O_RI + BB*NPTS;
static constexpr long O_GV  = O_SC + BB*NPTS;                  // 8*2112
static constexpr long O_CV  = O_GV + BB*2112;                  // 8*1024
static constexpr long O_MU  = O_CV + BB*1024;
static constexpr long O_IS  = O_MU + 1024;
// transposed-weight region
static constexpr long LSZ   = 245760;                          // per n2p layer
static constexpr long O_WT  = O_IS + 1024;                     // 3 layers
static constexpr long O_WE  = O_WT + 3*LSZ;                    // 4 x 16384 edge
static constexpr long O_W5  = O_WE + 4*16384;                  // 5 x 16384
static constexpr long O_WC  = O_W5 + 5*16384;                  // 131072
static constexpr long O_WC2 = O_WC + 131072;                   // 131072
static constexpr long O_WC3 = O_WC2+ 131072;                   // 262144
static constexpr long O_WC4 = O_WC3+ 262144;                   // 12800
static constexpr long POOLSZ= O_WC4 + 12800;

__device__ __align__(128) float g_pool[POOLSZ];
__device__ int g_ipool[(long)BB*NPTS*KNB + BB*MSEL];
static constexpr long SELOFF = (long)BB*NPTS*KNB;

// ---------------- fp32 128x128x8 strided-batch TN SGEMM (R4, bit-exact) ---
// C[b,i,j] = sum_k A[b*abs + k*ask + i*asi] * B[b*bbs + k*bsk + j*bsj]
__global__ __launch_bounds__(256) void gemm_tn(
    const float* __restrict__ A, const float* __restrict__ B,
    float* __restrict__ C, int Kd, int I, int J,
    long abs_, long ask, long asi,
    long bbs, long bsk, long bsj, long cbs)
{
    __shared__ float As[8][128];
    __shared__ float Bs[8][128];
    const int tid = threadIdx.x;
    const int tx = tid & 15, ty = tid >> 4;
    A += (long)blockIdx.z * abs_; B += (long)blockIdx.z * bbs;
    C += (long)blockIdx.z * cbs;
    const int i0 = blockIdx.y * 128, j0 = blockIdx.x * 128;
    const int li = tid & 127;
    const int k00 = tid >> 7;            // 0 or 1
    const int ia = i0 + li, jb = j0 + li;
    float acc[8][8] = {};
    float pa[4], pb[4];
#pragma unroll
    for (int u = 0; u < 4; u++) {
        int kk = k00 + u*2;
        pa[u] = (ia < I && kk < Kd) ? A[(long)kk*ask + (long)ia*asi] : 0.f;
        pb[u] = (jb < J && kk < Kd) ? B[(long)kk*bsk + (long)jb*bsj] : 0.f;
    }
    for (int k0 = 0; k0 < Kd; k0 += 8) {
#pragma unroll
        for (int u = 0; u < 4; u++) {
            As[k00 + u*2][li] = pa[u];
            Bs[k00 + u*2][li] = pb[u];
        }
        __syncthreads();
        int kn = k0 + 8;
        if (kn < Kd) {
#pragma unroll
            for (int u = 0; u < 4; u++) {
                int kk = kn + k00 + u*2;
                pa[u] = (ia < I && kk < Kd) ? A[(long)kk*ask + (long)ia*asi] : 0.f;
                pb[u] = (jb < J && kk < Kd) ? B[(long)kk*bsk + (long)jb*bsj] : 0.f;
            }
        }
#pragma unroll
        for (int kk = 0; kk < 8; kk++) {
            float4 a0 = *(const float4*)&As[kk][ty*8];
            float4 a1 = *(const float4*)&As[kk][ty*8 + 4];
            float4 b0 = *(const float4*)&Bs[kk][tx*8];
            float4 b1 = *(const float4*)&Bs[kk][tx*8 + 4];
            float ar[8] = {a0.x,a0.y,a0.z,a0.w,a1.x,a1.y,a1.z,a1.w};
            float br[8] = {b0.x,b0.y,b0.z,b0.w,b1.x,b1.y,b1.z,b1.w};
#pragma unroll
            for (int a = 0; a < 8; a++)
#pragma unroll
                for (int b2 = 0; b2 < 8; b2++) acc[a][b2] += ar[a]*br[b2];
        }
        __syncthreads();
    }
#pragma unroll
    for (int a = 0; a < 8; a++) {
        int i = i0 + ty*8 + a;
        if (i >= I) continue;
        int j = j0 + tx*8;
        if (j + 7 < J) {
            *(float4*)&C[(long)i*J + j]     = make_float4(acc[a][0],acc[a][1],acc[a][2],acc[a][3]);
            *(float4*)&C[(long)i*J + j + 4] = make_float4(acc[a][4],acc[a][5],acc[a][6],acc[a][7]);
        } else {
#pragma unroll
            for (int b2 = 0; b2 < 8; b2++)
                if (j + b2 < J) C[(long)i*J + j + b2] = acc[a][b2];
        }
    }
}

// ---------------- 3xTF32 tensor-core strided-batch TN GEMM ----------------
// C[b,i,j] = sum_k A[b*abs + k*ask + i] * B[b*bbs + k*bsk + j]
// Used ONLY on post-selection (smooth) paths.
__device__ __forceinline__ unsigned f2hi(float x) {
    unsigned u = __float_as_uint(x);
    return (u + 0x1000u) & 0xFFFFE000u;
}
__device__ __forceinline__ unsigned f2lo(float x, unsigned hi) {
    float lo = x - __uint_as_float(hi);
    return __float_as_uint(lo) & 0xFFFFE000u;
}
__device__ __forceinline__ void mma_tf32(float* c, const unsigned* a, const unsigned* b) {
    asm volatile(
      "mma.sync.aligned.m16n8k8.row.col.f32.tf32.tf32.f32 "
      "{%0,%1,%2,%3}, {%4,%5,%6,%7}, {%8,%9}, {%0,%1,%2,%3};\n"
      : "+f"(c[0]), "+f"(c[1]), "+f"(c[2]), "+f"(c[3])
      : "r"(a[0]), "r"(a[1]), "r"(a[2]), "r"(a[3]), "r"(b[0]), "r"(b[1]));
}

__global__ __launch_bounds__(256) void gemm_tc(
    const float* __restrict__ A, const float* __restrict__ B, float* __restrict__ C,
    int Kd, int I, int J, long abs_, long ask, long bbs, long bsk, long cbs)
{
    __shared__ float As[16][132];
    __shared__ float Bs[16][132];
    const int tid = threadIdx.x;
    const int lane = tid & 31, w = tid >> 5;
    const int wr = w >> 2, wc = w & 3;       // warp grid 2 x 4
    const int g = lane >> 2, t = lane & 3;   // quad layout
    A += (long)blockIdx.z * abs_; B += (long)blockIdx.z * bbs;
    C += (long)blockIdx.z * cbs;
    const int i0 = blockIdx.y * 128, j0 = blockIdx.x * 128;
    const bool fa = (i0 + 128 <= I), fb = (j0 + 128 <= J);
    float acc[4][4][4];
#pragma unroll
    for (int a = 0; a < 4; a++)
#pragma unroll
        for (int b2 = 0; b2 < 4; b2++)
#pragma unroll
            for (int u = 0; u < 4; u++) acc[a][b2][u] = 0.f;

    for (int k0 = 0; k0 < Kd; k0 += 16) {
#pragma unroll
        for (int it = 0; it < 2; it++) {
            int idx = tid + it*256;
            int kk = idx >> 5, i4 = (idx & 31) * 4;
            int kg = k0 + kk;
            float4 va = make_float4(0.f,0.f,0.f,0.f);
            float4 vb = make_float4(0.f,0.f,0.f,0.f);
            if (kg < Kd) {
                if (fa) va = *(const float4*)&A[(long)kg*ask + i0 + i4];
                else {
                    float* pv = &va.x;
#pragma unroll
                    for (int u = 0; u < 4; u++)
                        if (i0 + i4 + u < I) pv[u] = A[(long)kg*ask + i0 + i4 + u];
                }
                if (fb) vb = *(const float4*)&B[(long)kg*bsk + j0 + i4];
                else {
                    float* pv = &vb.x;
#pragma unroll
                    for (int u = 0; u < 4; u++)
                        if (j0 + i4 + u < J) pv[u] = B[(long)kg*bsk + j0 + i4 + u];
                }
            }
            *(float4*)&As[kk][i4] = va;
            *(float4*)&Bs[kk][i4] = vb;
        }
        __syncthreads();
#pragma unroll
        for (int s = 0; s < 2; s++) {
            const int kb = s*8;
            unsigned bhi[4][2], blo[4][2];
#pragma unroll
            for (int nt = 0; nt < 4; nt++) {
                float b0 = Bs[kb + t][wc*32 + nt*8 + g];
                float b1 = Bs[kb + t + 4][wc*32 + nt*8 + g];
                bhi[nt][0] = f2hi(b0); blo[nt][0] = f2lo(b0, bhi[nt][0]);
                bhi[nt][1] = f2hi(b1); blo[nt][1] = f2lo(b1, bhi[nt][1]);
            }
#pragma unroll
            for (int mt = 0; mt < 4; mt++) {
                float a0 = As[kb + t][wr*64 + mt*16 + g];
                float a1 = As[kb + t][wr*64 + mt*16 + g + 8];
                float a2 = As[kb + t + 4][wr*64 + mt*16 + g];
                float a3 = As[kb + t + 4][wr*64 + mt*16 + g + 8];
                unsigned ahi[4], alo[4];
                ahi[0] = f2hi(a0); alo[0] = f2lo(a0, ahi[0]);
                ahi[1] = f2hi(a1); alo[1] = f2lo(a1, ahi[1]);
                ahi[2] = f2hi(a2); alo[2] = f2lo(a2, ahi[2]);
                ahi[3] = f2hi(a3); alo[3] = f2lo(a3, ahi[3]);
#pragma unroll
                for (int nt = 0; nt < 4; nt++) {
                    mma_tf32(acc[mt][nt], alo, bhi[nt]);
                    mma_tf32(acc[mt][nt], ahi, blo[nt]);
                    mma_tf32(acc[mt][nt], ahi, bhi[nt]);
                }
            }
        }
        __syncthreads();
    }
#pragma unroll
    for (int mt = 0; mt < 4; mt++) {
#pragma unroll
        for (int nt = 0; nt < 4; nt++) {
            int i = i0 + wr*64 + mt*16 + g;
            int j = j0 + wc*32 + nt*8 + t*2;
            if (j < J) {
                if (i < I) {
                    float2 v = make_float2(acc[mt][nt][0], acc[mt][nt][1]);
                    *(float2*)&C[(long)i*J + j] = v;
                }
                if (i + 8 < I) {
                    float2 v = make_float2(acc[mt][nt][2], acc[mt][nt][3]);
                    *(float2*)&C[(long)(i+8)*J + j] = v;
                }
            }
        }
    }
}

// WT[c*O + o] = W[o*ld + c0 + c]
__global__ void wt_k(const float* __restrict__ W, float* __restrict__ WT,
                     int O, int Cin, int ld, int c0)
{
    int i = blockIdx.x*256 + threadIdx.x;
    if (i >= O*Cin) return;
    int c = i / O, o = i % O;
    WT[i] = W[(long)o*ld + c0 + c];
}

// transposed edge weight split: WdT[c*128+o] = W1-W2, W2T[c*128+o] = W2
__global__ void wdiff_k(const float* __restrict__ W, float* __restrict__ WdT,
                        float* __restrict__ W2T, int Cin)
{
    int i = blockIdx.x*256 + threadIdx.x;
    if (i >= Cin*128) return;
    int c = i / 128, o = i % 128;
    float w1 = W[(long)o*2*Cin + c], w2 = W[(long)o*2*Cin + Cin + c];
    WdT[i] = w1 - w2; W2T[i] = w2;
}

// (b,n,c) -> (b,c,n)
__global__ void transpose_nc(const float* __restrict__ X, float* __restrict__ Y,
                             int C, int Np)
{
    __shared__ float t[32][33];
    int b = blockIdx.z;
    int n0 = blockIdx.x*32, c0 = blockIdx.y*32;
    for (int yy = threadIdx.y; yy < 32; yy += 8) {
        int n = n0 + yy, c = c0 + threadIdx.x;
        if (n < Np && c < C) t[yy][threadIdx.x] = X[((long)b*Np + n)*C + c];
    }
    __syncthreads();
    for (int yy = threadIdx.y; yy < 32; yy += 8) {
        int c = c0 + yy, n = n0 + threadIdx.x;
        if (n < Np && c < C) Y[((long)b*C + c)*Np + n] = t[threadIdx.x][yy];
    }
}

// sq[b,n] = sum_c X[b,c,n]^2
__global__ void colnorm_k(const float* __restrict__ X, float* __restrict__ sq,
                          int C, int Np)
{
    int i = blockIdx.x*blockDim.x + threadIdx.x;
    if (i >= BB*Np) return;
    int b = i/Np, n = i%Np;
    const float* p = X + (long)b*C*Np + n;
    float s = 0.f;
    for (int c = 0; c < C; c++) { float v = p[(long)c*Np]; s += v*v; }
    sq[i] = s;
}

// per-row top-32 smallest distances, tie-break lower index (matches jax)
__global__ void knn_topk(const float* __restrict__ S, const float* __restrict__ sq,
                         int* __restrict__ idx, int Np)
{
    extern __shared__ float sd[];
    __shared__ float wv[8]; __shared__ int wi[8];
    int bn = blockIdx.x, b = bn/Np, n = bn%Np, tid = threadIdx.x;
    const float* Srow = S + ((long)b*Np + n)*Np;
    float sn = sq[(long)b*Np + n];
    for (int m = tid; m < Np; m += 256)
        sd[m] = sn - 2.f*Srow[m] + sq[(long)b*Np + m];
    __syncthreads();
    int lane = tid & 31, w = tid >> 5;
    for (int k = 0; k < KNB; k++) {
        float bv = FLT_MAX; int bi = 0x7fffffff;
        for (int m = tid; m < Np; m += 256) {
            float v = sd[m];
            if (v < bv) { bv = v; bi = m; }
        }
#pragma unroll
        for (int o = 16; o > 0; o >>= 1) {
            float ov = __shfl_down_sync(0xffffffffu, bv, o);
            int   oi = __shfl_down_sync(0xffffffffu, bi, o);
            if (ov < bv || (ov == bv && oi < bi)) { bv = ov; bi = oi; }
        }
        if (lane == 0) { wv[w] = bv; wi[w] = bi; }
        __syncthreads();
        if (tid == 0) {
            float rv = wv[0]; int ri = wi[0];
            for (int j = 1; j < 8; j++)
                if (wv[j] < rv || (wv[j] == rv && wi[j] < ri)) { rv = wv[j]; ri = wi[j]; }
            idx[((long)b*Np + n)*KNB + k] = ri;
            sd[ri] = FLT_MAX;
        }
        __syncthreads();
    }
}

// Ut,Vt in (b,n,o); outputs max/sum/sumsq over k in (b,o,n)
__global__ void edge_assemble(const float* __restrict__ Ut, const float* __restrict__ Vt,
                              const int* __restrict__ idx,
                              float* __restrict__ Ym, float* __restrict__ Ys,
                              float* __restrict__ Yq, int Np)
{
    int bn = blockIdx.x, b = bn/Np, o = threadIdx.x;
    float u = Ut[(long)bn*128 + o];
    const int* ip = idx + (long)bn*KNB;
    const float* vb = Vt + (long)b*Np*128;
    float mx = -FLT_MAX, s = 0.f, q = 0.f;
#pragma unroll 4
    for (int k = 0; k < KNB; k++) {
        int m = ip[k];
        float v = u + vb[(long)m*128 + o];
        mx = fmaxf(mx, v); s += v; q += v*v;
    }
    int n = bn % Np;
    long off = ((long)b*128 + o)*Np + n;
    Ym[off] = mx; Ys[off] = s; Yq[off] = q;
}

__global__ void stats_sums(const float* __restrict__ S1, const float* __restrict__ S2,
                           float* __restrict__ mu, float* __restrict__ is,
                           int O, int Np, long cnt)
{
    int o = blockIdx.x, tid = threadIdx.x;
    double s = 0, q = 0;
    for (int b = 0; b < BB; b++) {
        const float* p1 = S1 + ((long)b*O + o)*Np;
        const float* p2 = S2 + ((long)b*O + o)*Np;
        for (int n = tid; n < Np; n += 256) { s += p1[n]; q += p2[n]; }
    }
    __shared__ double ss[256], qq[256];
    ss[tid] = s; qq[tid] = q; __syncthreads();
    for (int st = 128; st > 0; st >>= 1) {
        if (tid < st) { ss[tid] += ss[tid+st]; qq[tid] += qq[tid+st]; }
        __syncthreads();
    }
    if (tid == 0) {
        double m = ss[0]/(double)cnt, v = qq[0]/(double)cnt - m*m;
        mu[o] = (float)m; is[o] = (float)(1.0/sqrt(v + 1e-5));
    }
}

__global__ void stats_tensor(const float* __restrict__ X, float* __restrict__ mu,
                             float* __restrict__ is, int O, int Np, long cnt)
{
    int o = blockIdx.x, tid = threadIdx.x;
    double s = 0, q = 0;
    for (int b = 0; b < BB; b++) {
        const float* p = X + ((long)b*O + o)*Np;
        for (int n = tid; n < Np; n += 256) { double v = p[n]; s += v; q += v*v; }
    }
    __shared__ double ss[256], qq[256];
    ss[tid] = s; qq[tid] = q; __syncthreads();
    for (int st = 128; st > 0; st >>= 1) {
        if (tid < st) { ss[tid] += ss[tid+st]; qq[tid] += qq[tid+st]; }
        __syncthreads();
    }
    if (tid == 0) {
        double m = ss[0]/(double)cnt, v = qq[0]/(double)cnt - m*m;
        mu[o] = (float)m; is[o] = (float)(1.0/sqrt(v + 1e-5));
    }
}

__global__ void bn_leaky(const float* __restrict__ X, const float* __restrict__ res,
                         float* __restrict__ Y, const float* __restrict__ mu,
                         const float* __restrict__ is, int O, int Np, long total)
{
    long i = (long)blockIdx.x*blockDim.x + threadIdx.x;
    if (i >= total) return;
    int o = (int)((i / Np) % O);
    float v = (X[i] - mu[o]) * is[o];
    v = v > 0.f ? v : 0.2f*v;
    Y[i] = res ? res[i] + v : v;
}

__global__ void concat2_k(const float* __restrict__ A, const float* __restrict__ B,
                          float* __restrict__ H, int C, int Np, long total)
{
    long i = (long)blockIdx.x*blockDim.x + threadIdx.x;
    if (i >= total) return;
    long per = (long)2*C*Np;
    int b = (int)(i/per); long r = i % per;
    int c = (int)(r/Np), n = (int)(r%Np);
    H[i] = (c < C) ? A[((long)b*C + c)*Np + n] : B[((long)b*C + c - C)*Np + n];
}

// warp-per-query local attention; qt/kt/vt/out in (b,n,c), c=128, K=32
__global__ void n2p_core(const float* __restrict__ qt, const float* __restrict__ kt,
                         const float* __restrict__ vt, const int* __restrict__ idx,
                         float* __restrict__ outt, int Np, float scale)
{
    __shared__ float qsh[4][128];
    int warp = threadIdx.x >> 5, lane = threadIdx.x & 31;
    long bn = (long)blockIdx.x*4 + warp;
    int b = (int)(bn/Np), n = (int)(bn%Np);
    const float* qp = qt + ((long)b*Np + n)*128;
    for (int c = lane; c < 128; c += 32) qsh[warp][c] = qp[c];
    __syncwarp();
    int m = idx[((long)b*Np + n)*KNB + lane];
    const float4* krow = (const float4*)(kt + ((long)b*Np + m)*128);
    float dot = 0.f;
#pragma unroll
    for (int c4 = 0; c4 < 32; c4++) {
        float4 kv = krow[c4];
        dot += qsh[warp][c4*4+0]*kv.x + qsh[warp][c4*4+1]*kv.y +
               qsh[warp][c4*4+2]*kv.z + qsh[warp][c4*4+3]*kv.w;
    }
    float logit = dot * scale, mx = logit;
#pragma unroll
    for (int o = 16; o > 0; o >>= 1) mx = fmaxf(mx, __shfl_xor_sync(0xffffffffu, mx, o));
    float e = __expf(logit - mx), sum = e;
#pragma unroll
    for (int o = 16; o > 0; o >>= 1) sum += __shfl_xor_sync(0xffffffffu, sum, o);
    float a = e / sum;
    const float* vbase = vt + (long)b*Np*128;
    float acc[4] = {0.f, 0.f, 0.f, 0.f};
#pragma unroll
    for (int k = 0; k < KNB; k++) {
        float ak = __shfl_sync(0xffffffffu, a, k);
        int  mk = __shfl_sync(0xffffffffu, m, k);
        const float* vr = vbase + (long)mk*128;
#pragma unroll
        for (int cb = 0; cb < 4; cb++) acc[cb] += ak * vr[cb*32 + lane];
    }
    float* op = outt + ((long)b*Np + n)*128;
#pragma unroll
    for (int cb = 0; cb < 4; cb++) op[cb*32 + lane] = acc[cb];
}

// pass 1: rmax[bn] = scale * max_m S[bn, m]
__global__ void row_max(const float* __restrict__ S, float* __restrict__ rmax,
                        int Np, float scale)
{
    __shared__ float red[256];
    long bn = blockIdx.x; int tid = threadIdx.x;
    const float* row = S + bn*Np;
    float mx = -FLT_MAX;
    for (int m = tid; m < Np; m += 256) mx = fmaxf(mx, row[m]);
    red[tid] = mx; __syncthreads();
    for (int s = 128; s > 0; s >>= 1) {
        if (tid < s) red[tid] = fmaxf(red[tid], red[tid+s]);
        __syncthreads();
    }
    if (tid == 0) rmax[bn] = red[0]*scale;
}

// pass 2: S <- exp(S*scale - rmax), rinv[bn] = 1/rowsum
__global__ void row_exp(float* __restrict__ S, const float* __restrict__ rmax,
                        float* __restrict__ rinv, int Np, float scale)
{
    __shared__ float red[256];
    long bn = blockIdx.x; int tid = threadIdx.x;
    float* row = S + bn*Np;
    float M = rmax[bn], sum = 0.f;
    for (int m = tid; m < Np; m += 256) {
        float e = __expf(row[m]*scale - M);
        row[m] = e; sum += e;
    }
    red[tid] = sum; __syncthreads();
    for (int s = 128; s > 0; s >>= 1) {
        if (tid < s) red[tid] += red[tid+s];
        __syncthreads();
    }
    if (tid == 0) rinv[bn] = 1.f/red[0];
}

// pass 3: score[b,m] = (1/Np) * sum_n P[n,m] * rinv[n]   (no exp)
__global__ void col_score(const float* __restrict__ S, const float* __restrict__ rinv,
                          float* __restrict__ score, int Np)
{
    __shared__ float rsh[NPTS];
    int b = blockIdx.y;
    int m = blockIdx.x*256 + threadIdx.x;
    for (int n = threadIdx.x; n < Np; n += 256) rsh[n] = rinv[(long)b*Np + n];
    __syncthreads();
    if (m >= Np) return;
    const float* Sb = S + (long)b*Np*Np;
    float acc = 0.f;
#pragma unroll 4
    for (int n = 0; n < Np; n++) acc += Sb[(long)n*Np + m]*rsh[n];
    score[(long)b*Np + m] = acc * (1.f/Np);
}

__global__ void topM_select(const float* __restrict__ score, int* __restrict__ sel,
                            int Np, int M)
{
    extern __shared__ float sc[];
    int b = blockIdx.x, tid = threadIdx.x;
    for (int m = tid; m < Np; m += 256) sc[m] = score[(long)b*Np + m];
    __syncthreads();
    for (int m = tid; m < Np; m += 256) {
        float v = sc[m];
        int r = 0;
        for (int j = 0; j < Np; j++) {
            float u = sc[j];
            r += (u > v) || (u == v && j < m);
        }
        if (r < M) sel[b*M + r] = m;
    }
}

__global__ void gather_cols(const float* __restrict__ X, const int* __restrict__ sel,
                            float* __restrict__ Y, int C, int Nsrc, int Mdst, long total)
{
    long i = (long)blockIdx.x*blockDim.x + threadIdx.x;
    if (i >= total) return;
    long per = (long)C*Mdst;
    int b = (int)(i/per); long r = i % per;
    int c = (int)(r/Mdst), j = (int)(r%Mdst);
    Y[i] = X[((long)b*C + c)*Nsrc + sel[b*Mdst + j]];
}

__global__ void softmax_rows(float* __restrict__ S, int cols, float scale)
{
    extern __shared__ float buf[];
    __shared__ float red[256];
    long row = blockIdx.x;
    int tid = threadIdx.x;
    float* p = S + row*cols;
    float mx = -FLT_MAX;
    for (int j = tid; j < cols; j += 256) { float v = p[j]*scale; buf[j] = v; mx = fmaxf(mx, v); }
    red[tid] = mx; __syncthreads();
    for (int s = 128; s > 0; s >>= 1) {
        if (tid < s) red[tid] = fmaxf(red[tid], red[tid+s]);
        __syncthreads();
    }
    float M = red[0]; __syncthreads();
    float sum = 0.f;
    for (int j = tid; j < cols; j += 256) { float e = __expf(buf[j]-M); buf[j] = e; sum += e; }
    red[tid] = sum; __syncthreads();
    for (int s = 128; s > 0; s >>= 1) {
        if (tid < s) red[tid] += red[tid+s];
        __syncthreads();
    }
    float inv = 1.f/red[0];
    for (int j = tid; j < cols; j += 256) p[j] = buf[j]*inv;
}

__global__ void add2_k(const float* __restrict__ A, const float* __restrict__ B,
                       float* __restrict__ Y, long total)
{
    long i = (long)blockIdx.x*blockDim.x + threadIdx.x;
    if (i < total) Y[i] = A[i] + B[i];
}

__global__ void chan_maxmean(const float* __restrict__ X, float* __restrict__ gvec)
{
    __shared__ float rm[256], rs[256];
    int bo = blockIdx.x, b = bo/1024, o = bo%1024, tid = threadIdx.x;
    const float* p = X + (long)bo*NPTS;
    float mx = -FLT_MAX, s = 0.f;
    for (int n = tid; n < NPTS; n += 256) { float v = p[n]; mx = fmaxf(mx, v); s += v; }
    rm[tid] = mx; rs[tid] = s; __syncthreads();
    for (int st = 128; st > 0; st >>= 1) {
        if (tid < st) { rm[tid] = fmaxf(rm[tid], rm[tid+st]); rs[tid] += rs[tid+st]; }
        __syncthreads();
    }
    if (tid == 0) {
        gvec[(long)b*2112 + o]        = rm[0];
        gvec[(long)b*2112 + 1024 + o] = rs[0]*(1.f/NPTS);
    }
}

__global__ void cid_k(const float* __restrict__ W, const float* __restrict__ cat,
                      float* __restrict__ gvec)
{
    int o = threadIdx.x;
    if (o >= 64) return;
    float y[8]; double s = 0, q = 0;
    for (int b = 0; b < 8; b++) {
        float a = 0.f;
        for (int c = 0; c < 16; c++) a += W[o*16+c]*cat[b*16+c];
        y[b] = a; s += a; q += (double)a*a;
    }
    double m = s/8.0, v = q/8.0 - m*m;
    float is = (float)(1.0/sqrt(v + 1e-5));
    for (int b = 0; b < 8; b++) {
        float t = (y[b] - (float)m)*is;
        gvec[(long)b*2112 + 2048 + o] = t > 0.f ? t : 0.2f*t;
    }
}

__global__ void cvec_k(const float* __restrict__ Wc2, const float* __restrict__ gvec,
                       float* __restrict__ cvec)
{
    long gid = (long)blockIdx.x*256 + threadIdx.x;
    int warp = (int)(gid >> 5), lane = (int)(gid & 31);
    if (warp >= BB*1024) return;
    int b = warp/1024, o = warp%1024;
    const float* wr = Wc2 + (long)o*2240;
    const float* gv = gvec + (long)b*2112;
    float s = 0.f;
    for (int j = lane; j < 2112; j += 32) s += wr[j]*gv[j];
#pragma unroll
    for (int t = 16; t > 0; t >>= 1) s += __shfl_down_sync(0xffffffffu, s, t);
    if (lane == 0) cvec[warp] = s;
}

__global__ void add_bias_bo(float* __restrict__ X, const float* __restrict__ cst,
                            int Np, long total)
{
    long i = (long)blockIdx.x*blockDim.x + threadIdx.x;
    if (i < total) X[i] += cst[i/Np];
}

// ---------------- host orchestration --------------------------------------
static void G(const float* A, const float* B, float* C, int Kd, int I, int J,
              long abs_, long ask, long asi, long bbs, long bsk, long bsj, long cbs)
{
    dim3 grid((J+127)/128, (I+127)/128, BB);
    gemm_tn<<<grid, 256>>>(A, B, C, Kd, I, J, abs_, ask, asi, bbs, bsk, bsj, cbs);
}

static void Gt(const float* A, const float* B, float* C, int Kd, int I, int J,
               long abs_, long ask, long bbs, long bsk, long cbs)
{
    dim3 grid((J+127)/128, (I+127)/128, BB);
    gemm_tc<<<grid, 256>>>(A, B, C, Kd, I, J, abs_, ask, bbs, bsk, cbs);
}

static void BN(const float* X, const float* res, float* Y, float* mu, float* is,
               int O, int Np)
{
    stats_tensor<<<O, 256>>>(X, mu, is, O, Np, (long)BB*Np);
    long tot = (long)BB*O*Np;
    bn_leaky<<<(int)((tot+255)/256), 256>>>(X, res, Y, mu, is, O, Np, tot);
}

static void KNN(const float* X, int Cin, int Np, float* P, int* idx)
{
    colnorm_k<<<(BB*Np+255)/256, 256>>>(X, P+O_SQ, Cin, Np);
    G(X, X, P+O_S, Cin, Np, Np, (long)Cin*Np, Np, 1, (long)Cin*Np, Np, 1, (long)Np*Np);
    knn_topk<<<BB*Np, 256, Np*4>>>(P+O_S, P+O_SQ, idx, Np);
}

static void N2P(const float* X, int Cin, int Np, const float* WT,
                float* outb, float* P, int* idx, bool tc)
{
    const float* WqT  = WT;
    const float* WkT  = WT + 32768;
    const float* WvT  = WT + 65536;
    const float* WoT  = WT + 98304;
    const float* Wf1T = WT + 114688;
    const float* Wf2T = WT + 180224;
    KNN(X, Cin, Np, P, idx);               // selection path: always fp32
    long XB = (long)Cin*Np;
    // q/k/v in (b,n,c)
    if (tc) {
        Gt(X, WqT, P+O_T1, Cin, Np, 128, XB, Np, 0, 128, (long)Np*128);
        Gt(X, WkT, P+O_T2, Cin, Np, 128, XB, Np, 0, 128, (long)Np*128);
        Gt(X, WvT, P+O_T3, Cin, Np, 128, XB, Np, 0, 128, (long)Np*128);
    } else {
        G(X, WqT, P+O_T1, Cin, Np, 128, XB, Np, 1, 0, 128, 1, (long)Np*128);
        G(X, WkT, P+O_T2, Cin, Np, 128, XB, Np, 1, 0, 128, 1, (long)Np*128);
        G(X, WvT, P+O_T3, Cin, Np, 128, XB, Np, 1, 0, 128, 1, (long)Np*128);
    }
    n2p_core<<<BB*Np/4, 128>>>(P+O_T1, P+O_T2, P+O_T3, idx, P+O_T4, Np, SCL);
    transpose_nc<<<dim3((Np+31)/32, 4, BB), dim3(32,8)>>>(P+O_T4, P+O_T5, 128, Np);
    if (tc) Gt(WoT, P+O_T5, P+O_T6, 128, 128, Np, 0, 128, (long)128*Np, Np, (long)128*Np);
    else    G(WoT, P+O_T5, P+O_T6, 128, 128, Np, 0, 128, 1, (long)128*Np, Np, 1, (long)128*Np);
    BN(P+O_T6, nullptr, P+O_Y, P+O_MU, P+O_IS, 128, Np);
    if (tc) Gt(Wf1T, P+O_Y, P+O_F, 128, 512, Np, 0, 512, (long)128*Np, Np, (long)512*Np);
    else    G(Wf1T, P+O_Y, P+O_F, 128, 512, Np, 0, 512, 1, (long)128*Np, Np, 1, (long)512*Np);
    BN(P+O_F, nullptr, P+O_F, P+O_MU, P+O_IS, 512, Np);
    if (tc) Gt(Wf2T, P+O_F, P+O_T6, 512, 128, Np, 0, 128, (long)512*Np, Np, (long)128*Np);
    else    G(Wf2T, P+O_F, P+O_T6, 512, 128, Np, 0, 128, 1, (long)512*Np, Np, 1, (long)128*Np);
    BN(P+O_T6, P+O_Y, outb, P+O_MU, P+O_IS, 128, Np);
}

static void EDGE(const float* X, int Cin, const float* W, float* wdT, float* w2T,
                 float* e, float* P, int* idx)
{
    KNN(X, Cin, NPTS, P, idx);
    wdiff_k<<<(Cin*128+255)/256, 256>>>(W, wdT, w2T, Cin);
    long XB = (long)Cin*NPTS;
    G(X, wdT, P+O_T1, Cin, NPTS, 128, XB, NPTS, 1, 0, 128, 1, (long)NPTS*128);  // Ut (b,n,o)
    G(X, w2T, P+O_T2, Cin, NPTS, 128, XB, NPTS, 1, 0, 128, 1, (long)NPTS*128);  // Vt (b,n,o)
    edge_assemble<<<BB*NPTS, 128>>>(P+O_T1, P+O_T2, idx, P+O_T3, P+O_T4, P+O_T5, NPTS);
    stats_sums<<<128, 256>>>(P+O_T4, P+O_T5, P+O_MU, P+O_IS, 128, NPTS, (long)BB*NPTS*KNB);
    long tot = (long)BB*128*NPTS;
    bn_leaky<<<(int)((tot+255)/256), 256>>>(P+O_T3, nullptr, e, P+O_MU, P+O_IS, 128, NPTS, tot);
}

extern "C" void kernel_launch(void* const* d_in, const int* in_sizes, int n_in,
                              void* d_out, int out_size)
{
    (void)in_sizes; (void)n_in; (void)out_size;
    static float* P = nullptr; static int* IP = nullptr;
    if (!P) {
        cudaGetSymbolAddress((void**)&P, g_pool);
        cudaGetSymbolAddress((void**)&IP, g_ipool);
    }
    const float* x   = (const float*)d_in[0];
    const float* cat = (const float*)d_in[1];
    const float* We0 = (const float*)d_in[2];
    const float* We1 = (const float*)d_in[3];
    const float* W[3][6];
    for (int l = 0; l < 3; l++)
        for (int j = 0; j < 6; j++) W[l][j] = (const float*)d_in[4 + l*6 + j];
    const float* Wdq = (const float*)d_in[22];
    const float* Wdk = (const float*)d_in[23];
    const float* Wuq = (const float*)d_in[24];
    const float* Wuk = (const float*)d_in[25];
    const float* Wuv = (const float*)d_in[26];
    const float* Wc  = (const float*)d_in[27];
    const float* Wc1 = (const float*)d_in[28];
    const float* Wc2 = (const float*)d_in[29];
    const float* Wc3 = (const float*)d_in[30];
    const float* Wc4 = (const float*)d_in[31];
    float* out = (float*)d_out;
    const int Np = NPTS, Mm = MSEL;
    int* sel = IP + SELOFF;

    // one independent wt_k first, then EDGE0 — positions knn_topk / heavy
    // kernels into the ncu capture window instead of trivial transposes.
    wt_k<<<(50*256+255)/256, 256>>>(Wc4, P+O_WC4, 50, 256, 256, 0);
    EDGE(x, 3, We0, P+O_WE, P+O_WE+16384, P+O_E0, P, IP);

    // ---- transpose remaining weights ----
    int cins[3] = {256, 128, 128};
    for (int l = 0; l < 3; l++) {
        float* base = P + O_WT + (long)l*LSZ;
        int ci = cins[l];
        wt_k<<<(128*ci+255)/256, 256>>>(W[l][0], base,          128, ci, ci, 0);
        wt_k<<<(128*ci+255)/256, 256>>>(W[l][1], base + 32768,  128, ci, ci, 0);
        wt_k<<<(128*ci+255)/256, 256>>>(W[l][2], base + 65536,  128, ci, ci, 0);
        wt_k<<<(128*128+255)/256, 256>>>(W[l][3], base + 98304, 128, 128, 128, 0);
        wt_k<<<(512*128+255)/256, 256>>>(W[l][4], base + 114688, 512, 128, 128, 0);
        wt_k<<<(128*512+255)/256, 256>>>(W[l][5], base + 180224, 128, 512, 512, 0);
    }
    wt_k<<<(128*128+255)/256, 256>>>(Wdq, P+O_W5,          128, 128, 128, 0);
    wt_k<<<(128*128+255)/256, 256>>>(Wdk, P+O_W5+16384,    128, 128, 128, 0);
    wt_k<<<(128*128+255)/256, 256>>>(Wuq, P+O_W5+32768,    128, 128, 128, 0);
    wt_k<<<(128*128+255)/256, 256>>>(Wuk, P+O_W5+49152,    128, 128, 128, 0);
    wt_k<<<(128*128+255)/256, 256>>>(Wuv, P+O_W5+65536,    128, 128, 128, 0);
    wt_k<<<(1024*128+255)/256, 256>>>(Wc,  P+O_WC,  1024, 128, 128, 0);
    wt_k<<<(1024*128+255)/256, 256>>>(Wc2, P+O_WC2, 1024, 128, 2240, 2112);
    wt_k<<<(256*1024+255)/256, 256>>>(Wc3, P+O_WC3, 256, 1024, 1024, 0);

    // ---- encoder ----
    EDGE(P+O_E0, 128, We1, P+O_WE+32768, P+O_WE+49152, P+O_E1, P, IP);
    {
        long tot = (long)BB*256*Np;
        concat2_k<<<(int)((tot+255)/256), 256>>>(P+O_E0, P+O_E1, P+O_H, 128, Np, tot);
    }
    N2P(P+O_H, 256, Np, P+O_WT, P+O_HF, P, IP, false);

    // ---- down_global (selection path: fp32) ----
    const float* WdqT = P+O_W5, *WdkT = P+O_W5+16384;
    const float* WuqT = P+O_W5+32768, *WukT = P+O_W5+49152, *WuvT = P+O_W5+65536;
    G(WdqT, P+O_HF, P+O_T1, 128, 128, Np, 0, 128, 1, (long)128*Np, Np, 1, (long)128*Np);
    G(WdkT, P+O_HF, P+O_T2, 128, 128, Np, 0, 128, 1, (long)128*Np, Np, 1, (long)128*Np);
    G(P+O_T1, P+O_T2, P+O_S, 128, Np, Np, (long)128*Np, Np, 1, (long)128*Np, Np, 1, (long)Np*Np);
    row_max<<<BB*Np, 256>>>(P+O_S, P+O_RM, Np, SCL);
    row_exp<<<BB*Np, 256>>>(P+O_S, P+O_RM, P+O_RI, Np, SCL);
    col_score<<<dim3(Np/256, BB), 256>>>(P+O_S, P+O_RI, P+O_SC, Np);
    topM_select<<<BB, 256, Np*4>>>(P+O_SC, sel, Np, Mm);
    {
        long tot = (long)BB*128*Mm;
        gather_cols<<<(int)((tot+255)/256), 256>>>(P+O_HF, sel, P+O_HD, 128, Np, Mm, tot);
    }
    N2P(P+O_HD, 128, Mm, P+O_WT+LSZ, P+O_HD2, P, IP, false);

    // ---- up_cross (feeds n2p2 kNN: fp32) ----
    G(WuqT, P+O_HF,  P+O_T1, 128, 128, Np, 0, 128, 1, (long)128*Np, Np, 1, (long)128*Np);
    G(WukT, P+O_HD2, P+O_T2, 128, 128, Mm, 0, 128, 1, (long)128*Mm, Mm, 1, (long)128*Mm);
    G(P+O_T1, P+O_T2, P+O_S, 128, Np, Mm, (long)128*Np, Np, 1, (long)128*Mm, Mm, 1, (long)Np*Mm);
    softmax_rows<<<BB*Np, 256, Mm*4>>>(P+O_S, Mm, SCL);
    transpose_nc<<<dim3((Np+31)/32, (Mm+31)/32, BB), dim3(32,8)>>>(P+O_S, P+O_B1, Mm, Np);
    G(P+O_HD2, WuvT, P+O_T3, 128, Mm, 128, (long)128*Mm, Mm, 1, 0, 128, 1, (long)Mm*128);
    G(P+O_T3, P+O_B1, P+O_T4, Mm, 128, Np, (long)Mm*128, 128, 1, (long)Mm*Np, Np, 1, (long)128*Np);
    add2_k<<<(int)((NT+255)/256), 256>>>(P+O_HF, P+O_T4, P+O_HU, NT);

    // ---- n2p2: kNN fp32, internals TC (post-selection smooth) ----
    N2P(P+O_HU, 128, Np, P+O_WT+2*LSZ, P+O_XT, P, IP, true);

    // ---- head (all post-selection: TC) ----
    Gt(P+O_WC, P+O_XT, P+O_B1, 128, 1024, Np, 0, 1024, (long)128*Np, Np, (long)1024*Np);
    BN(P+O_B1, nullptr, P+O_B1, P+O_MU, P+O_IS, 1024, Np);
    chan_maxmean<<<BB*1024, 256>>>(P+O_B1, P+O_GV);
    cid_k<<<1, 64>>>(Wc1, cat, P+O_GV);
    cvec_k<<<BB*1024/8, 256>>>(Wc2, P+O_GV, P+O_CV);
    Gt(P+O_WC2, P+O_XT, P+O_B2, 128, 1024, Np, 0, 1024, (long)128*Np, Np, (long)1024*Np);
    {
        long tot = (long)BB*1024*Np;
        add_bias_bo<<<(int)((tot+255)/256), 256>>>(P+O_B2, P+O_CV, Np, tot);
    }
    BN(P+O_B2, nullptr, P+O_B2, P+O_MU, P+O_IS, 1024, Np);
    Gt(P+O_WC3, P+O_B2, P+O_B1, 1024, 256, Np, 0, 256, (long)1024*Np, Np, (long)256*Np);
    BN(P+O_B1, nullptr, P+O_B1, P+O_MU, P+O_IS, 256, Np);
    Gt(P+O_WC4, P+O_B1, out, 256, 50, Np, 0, 50, (long)256*Np, Np, (long)50*Np);
}